// round 9
// baseline (speedup 1.0000x reference)
#include <cuda_runtime.h>
#include <cuda_bf16.h>
#include <math.h>

// ---------------- Problem constants ----------------
#define BB    16          // batch
#define PS    32
#define NTOK  1024        // PS*PS
#define DD    768
#define HEADS 8
#define HDIM  24
#define PROP  4
#define MCEN  16          // PROP*PROP
#define INNER 192         // HEADS*HDIM
#define HID   3072
#define T_TOT (BB*NTOK)   // 16384 tokens
#define BE    (BB*HEADS)  // 128

// ---------------- Scratch (device globals; no allocation APIs) ----------------
__device__ float g_x1 [T_TOT*DD];      // LN1(x)
__device__ float g_f  [T_TOT*INNER];   // f features   [t][e*24+c]
__device__ float g_v  [T_TOT*INNER];   // v features
__device__ float g_cn [BE*MCEN*HDIM];  // normalized f-centers
__device__ float g_vcen[BE*MCEN*HDIM]; // raw v-centers
__device__ int   g_assign[BE*NTOK];
__device__ float g_simval[BE*NTOK];
__device__ float g_outc[BE*MCEN*HDIM];
__device__ float g_oi [T_TOT*INNER];   // scattered cluster feature per token
__device__ float g_h  [T_TOT*DD];      // x + cluster out
__device__ float g_y1 [T_TOT*DD];      // LN2(h)
__device__ float g_act[T_TOT*HID];     // gelu(fc1)

// ---------------- LayerNorm over D=768, one block per token ----------------
__global__ void __launch_bounds__(256) ln_kernel(const float* __restrict__ x,
    const float* __restrict__ w, const float* __restrict__ b, float* __restrict__ out)
{
    int t = blockIdx.x;
    const float* xr = x + (size_t)t * DD;
    float* orow = out + (size_t)t * DD;
    int tid = threadIdx.x;
    float v0 = xr[tid], v1 = xr[tid + 256], v2 = xr[tid + 512];
    float s  = v0 + v1 + v2;
    float ss = v0*v0 + v1*v1 + v2*v2;
    #pragma unroll
    for (int o = 16; o; o >>= 1) {
        s  += __shfl_xor_sync(0xffffffffu, s,  o);
        ss += __shfl_xor_sync(0xffffffffu, ss, o);
    }
    __shared__ float rs[8], rss[8];
    if ((tid & 31) == 0) { rs[tid >> 5] = s; rss[tid >> 5] = ss; }
    __syncthreads();
    float S = 0.f, SS = 0.f;
    #pragma unroll
    for (int i = 0; i < 8; i++) { S += rs[i]; SS += rss[i]; }
    float mean = S * (1.f / DD);
    float var  = SS * (1.f / DD) - mean * mean;
    float rstd = rsqrtf(var + 1e-5f);
    orow[tid]       = (v0 - mean) * rstd * w[tid]       + b[tid];
    orow[tid + 256] = (v1 - mean) * rstd * w[tid + 256] + b[tid + 256];
    orow[tid + 512] = (v2 - mean) * rstd * w[tid + 512] + b[tid + 512];
}

// ---------------- Generic register-blocked SGEMM: C = epi(A * W^T + bias) ----------------
// A: [M][K] row-major, W: [Nn][K] row-major, C: [M][Nn].
// EPI: 0 = store, 1 = exact GELU, 2 = add residual R[M][Nn]
__device__ __forceinline__ float gelu_exact(float x) {
    return 0.5f * x * (1.f + erff(x * 0.70710678118654752440f));
}

template<int BM, int BN, int BK, int TM, int TN, int EPI>
__global__ void __launch_bounds__(256) sgemm_kernel(
    const float* __restrict__ A, const float* __restrict__ W,
    const float* __restrict__ bias, const float* __restrict__ R,
    float* __restrict__ C, int M, int Nn, int K)
{
    __shared__ __align__(16) float As[BK][BM];
    __shared__ __align__(16) float Ws[BK][BN];
    const int tid = threadIdx.x;
    const int m0 = blockIdx.y * BM;
    const int n0 = blockIdx.x * BN;
    constexpr int NT = BN / TN;
    const int ty = tid / NT;
    const int tx = tid % NT;
    const int rm  = ty * TM;
    const int cnb = tx * TN;

    float acc[TM][TN];
    #pragma unroll
    for (int i = 0; i < TM; i++)
        #pragma unroll
        for (int j = 0; j < TN; j++) acc[i][j] = 0.f;

    constexpr int K4  = BK / 4;
    constexpr int AV4 = BM * BK / 4;
    constexpr int WV4 = BN * BK / 4;

    for (int k0 = 0; k0 < K; k0 += BK) {
        #pragma unroll
        for (int v = tid; v < AV4; v += 256) {
            int m = v / K4, kq = v % K4;
            float4 t = *reinterpret_cast<const float4*>(&A[(size_t)(m0 + m) * K + k0 + kq * 4]);
            As[kq*4+0][m] = t.x; As[kq*4+1][m] = t.y; As[kq*4+2][m] = t.z; As[kq*4+3][m] = t.w;
        }
        #pragma unroll
        for (int v = tid; v < WV4; v += 256) {
            int n = v / K4, kq = v % K4;
            float4 t = *reinterpret_cast<const float4*>(&W[(size_t)(n0 + n) * K + k0 + kq * 4]);
            Ws[kq*4+0][n] = t.x; Ws[kq*4+1][n] = t.y; Ws[kq*4+2][n] = t.z; Ws[kq*4+3][n] = t.w;
        }
        __syncthreads();
        #pragma unroll
        for (int kk = 0; kk < BK; kk++) {
            float a[TM], bb[TN];
            #pragma unroll
            for (int i = 0; i < TM; i++) a[i] = As[kk][rm + i];
            #pragma unroll
            for (int j = 0; j < TN; j++) bb[j] = Ws[kk][cnb + j];
            #pragma unroll
            for (int i = 0; i < TM; i++)
                #pragma unroll
                for (int j = 0; j < TN; j++)
                    acc[i][j] = fmaf(a[i], bb[j], acc[i][j]);
        }
        __syncthreads();
    }

    #pragma unroll
    for (int i = 0; i < TM; i++) {
        int row = m0 + rm + i;
        #pragma unroll
        for (int j0 = 0; j0 < TN; j0 += 4) {
            int col = n0 + cnb + j0;
            float4 bv = *reinterpret_cast<const float4*>(&bias[col]);
            float4 o;
            o.x = acc[i][j0+0] + bv.x; o.y = acc[i][j0+1] + bv.y;
            o.z = acc[i][j0+2] + bv.z; o.w = acc[i][j0+3] + bv.w;
            if (EPI == 1) {
                o.x = gelu_exact(o.x); o.y = gelu_exact(o.y);
                o.z = gelu_exact(o.z); o.w = gelu_exact(o.w);
            } else if (EPI == 2) {
                float4 rv = *reinterpret_cast<const float4*>(&R[(size_t)row * Nn + col]);
                o.x += rv.x; o.y += rv.y; o.z += rv.z; o.w += rv.w;
            }
            *reinterpret_cast<float4*>(&C[(size_t)row * Nn + col]) = o;
        }
    }
}

// ---------------- Pooling: centers (mean over 8x8 spatial block) + normalize f-centers ----
__global__ void __launch_bounds__(384) pool_kernel()
{
    int be  = blockIdx.x;            // 0..127
    int bb  = be >> 3, e = be & 7;
    int tid = threadIdx.x;           // 384 = 16 m * 24 c
    int m = tid / HDIM, c = tid % HDIM;
    int pw = m >> 2, ph = m & 3;
    float sf = 0.f, sv = 0.f;
    #pragma unroll 4
    for (int ws = 0; ws < 8; ws++) {
        #pragma unroll
        for (int hs = 0; hs < 8; hs++) {
            int n = (pw * 8 + ws) * PS + ph * 8 + hs;
            size_t idx = (size_t)(bb * NTOK + n) * INNER + e * HDIM + c;
            sf += g_f[idx];
            sv += g_v[idx];
        }
    }
    sf *= (1.f / 64.f); sv *= (1.f / 64.f);
    __shared__ float cen_s[MCEN][HDIM];
    cen_s[m][c] = sf;
    __syncthreads();
    float ssq = 0.f;
    #pragma unroll
    for (int cc = 0; cc < HDIM; cc++) { float t = cen_s[m][cc]; ssq += t * t; }
    float denom = fmaxf(sqrtf(ssq), 1e-12f);
    size_t oidx = ((size_t)be * MCEN + m) * HDIM + c;
    g_cn[oidx]   = sf / denom;
    g_vcen[oidx] = sv;
}

// ---------------- Per-token similarity + argmax assignment ----------------
__global__ void __launch_bounds__(256) assign_kernel(const float* __restrict__ alpha_p,
                                                     const float* __restrict__ beta_p)
{
    int be = blockIdx.x;
    int bb = be >> 3, e = be & 7;
    __shared__ float cns[MCEN][HDIM];
    for (int t = threadIdx.x; t < MCEN * HDIM; t += blockDim.x)
        cns[t / HDIM][t % HDIM] = g_cn[(size_t)be * MCEN * HDIM + t];
    __syncthreads();
    float alpha = *alpha_p, beta = *beta_p;
    for (int n = threadIdx.x; n < NTOK; n += blockDim.x) {
        const float* xv = g_f + (size_t)(bb * NTOK + n) * INNER + e * HDIM;
        float x[HDIM]; float ss = 0.f;
        #pragma unroll
        for (int c = 0; c < HDIM; c++) { x[c] = xv[c]; ss += x[c] * x[c]; }
        float inv = 1.f / fmaxf(sqrtf(ss), 1e-12f);
        float best = -1e30f; int bm = 0;
        #pragma unroll
        for (int m = 0; m < MCEN; m++) {
            float d = 0.f;
            #pragma unroll
            for (int c = 0; c < HDIM; c++) d = fmaf(cns[m][c], x[c], d);
            d *= inv;
            float dist = sqrtf(fmaxf(2.f - 2.f * d, 1e-12f));
            float sp = beta + alpha * expf(-dist);
            float sim = sp > 0.f ? sp : 0.2f * sp;        // leaky_relu(·, 0.2)
            if (sim > best) { best = sim; bm = m; }       // first-max, matches jnp.argmax
        }
        g_assign[(size_t)be * NTOK + n] = bm;
        g_simval[(size_t)be * NTOK + n] = best;
    }
}

// ---------------- Deterministic per-(be,m) weighted reduce to centers ----------------
__global__ void __launch_bounds__(192) outc_kernel()
{
    int m  = blockIdx.x;     // 0..15
    int be = blockIdx.y;     // 0..127
    int bb = be >> 3, e = be & 7;
    int tid = threadIdx.x;   // 192 = 24 c * 8 g
    int c = tid % HDIM, g = tid / HDIM;
    float acc = 0.f; int cnt = 0;
    for (int n = g * 128; n < g * 128 + 128; n++) {
        int a = g_assign[(size_t)be * NTOK + n];
        if (a == m) {
            float s = g_simval[(size_t)be * NTOK + n];
            acc = fmaf(s, g_v[(size_t)(bb * NTOK + n) * INNER + e * HDIM + c], acc);
            cnt++;
        }
    }
    __shared__ float pa[8][HDIM];
    __shared__ int   pc[8];
    pa[g][c] = acc;
    if (c == 0) pc[g] = cnt;
    __syncthreads();
    if (g == 0) {
        float tot = 0.f; int ct = 0;
        #pragma unroll
        for (int gg = 0; gg < 8; gg++) { tot += pa[gg][c]; ct += pc[gg]; }
        size_t oidx = ((size_t)be * MCEN + m) * HDIM + c;
        g_outc[oidx] = (tot + g_vcen[oidx]) / ((float)ct + 1.f);
    }
}

// ---------------- Scatter center features back to tokens ----------------
__global__ void __launch_bounds__(256) oi_kernel()
{
    size_t idx = (size_t)blockIdx.x * blockDim.x + threadIdx.x;
    if (idx >= (size_t)T_TOT * INNER) return;
    int t = (int)(idx / INNER), i = (int)(idx % INNER);
    int bb = t >> 10, n = t & (NTOK - 1);
    int e = i / HDIM, c = i % HDIM;
    int be = bb * HEADS + e;
    int m = g_assign[(size_t)be * NTOK + n];
    g_oi[idx] = g_simval[(size_t)be * NTOK + n] * g_outc[((size_t)be * MCEN + m) * HDIM + c];
}

// ---------------- Launch ----------------
extern "C" void kernel_launch(void* const* d_in, const int* in_sizes, int n_in,
                              void* d_out, int out_size)
{
    const float* x      = (const float*)d_in[0];
    const float* ln1_w  = (const float*)d_in[1];
    const float* ln1_b  = (const float*)d_in[2];
    const float* f_w    = (const float*)d_in[3];
    const float* f_b    = (const float*)d_in[4];
    const float* v_w    = (const float*)d_in[5];
    const float* v_b    = (const float*)d_in[6];
    const float* proj_w = (const float*)d_in[7];
    const float* proj_b = (const float*)d_in[8];
    const float* alpha  = (const float*)d_in[9];
    const float* beta   = (const float*)d_in[10];
    const float* ln2_w  = (const float*)d_in[11];
    const float* ln2_b  = (const float*)d_in[12];
    const float* fc1_w  = (const float*)d_in[13];
    const float* fc1_b  = (const float*)d_in[14];
    const float* fc2_w  = (const float*)d_in[15];
    const float* fc2_b  = (const float*)d_in[16];
    float* out = (float*)d_out;

    float *p_x1, *p_f, *p_v, *p_oi, *p_h, *p_y1, *p_act;
    cudaGetSymbolAddress((void**)&p_x1,  g_x1);
    cudaGetSymbolAddress((void**)&p_f,   g_f);
    cudaGetSymbolAddress((void**)&p_v,   g_v);
    cudaGetSymbolAddress((void**)&p_oi,  g_oi);
    cudaGetSymbolAddress((void**)&p_h,   g_h);
    cudaGetSymbolAddress((void**)&p_y1,  g_y1);
    cudaGetSymbolAddress((void**)&p_act, g_act);

    // 1) LN1
    ln_kernel<<<T_TOT, 256>>>(x, ln1_w, ln1_b, p_x1);

    // 2,3) f and v projections: [16384,768] x [192,768]^T
    {
        dim3 grid(INNER / 64, T_TOT / 128);
        sgemm_kernel<128, 64, 8, 8, 4, 0><<<grid, 256>>>(p_x1, f_w, f_b, nullptr, p_f, T_TOT, INNER, DD);
        sgemm_kernel<128, 64, 8, 8, 4, 0><<<grid, 256>>>(p_x1, v_w, v_b, nullptr, p_v, T_TOT, INNER, DD);
    }

    // 4) pooling + center normalization
    pool_kernel<<<BE, 384>>>();

    // 5) per-token assignment
    assign_kernel<<<BE, 256>>>(alpha, beta);

    // 6) weighted reduce to centers (deterministic)
    outc_kernel<<<dim3(MCEN, BE), 192>>>();

    // 7) scatter back to tokens
    {
        int total = T_TOT * INNER;
        oi_kernel<<<(total + 255) / 256, 256>>>();
    }

    // 8) proj GEMM + residual x -> h : [16384,192] x [768,192]^T + x
    sgemm_kernel<128, 128, 8, 8, 8, 2><<<dim3(DD / 128, T_TOT / 128), 256>>>(
        p_oi, proj_w, proj_b, x, p_h, T_TOT, DD, INNER);

    // 9) LN2
    ln_kernel<<<T_TOT, 256>>>(p_h, ln2_w, ln2_b, p_y1);

    // 10) fc1 + exact GELU : [16384,768] x [3072,768]^T
    sgemm_kernel<128, 128, 8, 8, 8, 1><<<dim3(HID / 128, T_TOT / 128), 256>>>(
        p_y1, fc1_w, fc1_b, nullptr, p_act, T_TOT, HID, DD);

    // 11) fc2 + residual h -> out : [16384,3072] x [768,3072]^T + h
    sgemm_kernel<128, 128, 8, 8, 8, 2><<<dim3(DD / 128, T_TOT / 128), 256>>>(
        p_act, fc2_w, fc2_b, p_h, out, T_TOT, DD, HID);
}

// round 10
// speedup vs baseline: 1.0007x; 1.0007x over previous
#include <cuda_runtime.h>
#include <cuda_bf16.h>
#include <math.h>

// ---------------- Problem constants ----------------
#define BB    16          // batch
#define PS    32
#define NTOK  1024        // PS*PS
#define DD    768
#define HEADS 8
#define HDIM  24
#define PROP  4
#define MCEN  16          // PROP*PROP
#define INNER 192         // HEADS*HDIM
#define HID   3072
#define T_TOT (BB*NTOK)   // 16384 tokens
#define BE    (BB*HEADS)  // 128

// ---------------- Scratch (device globals; no allocation APIs) ----------------
__device__ float g_x1 [T_TOT*DD];      // LN1(x)
__device__ float g_f  [T_TOT*INNER];   // f features   [t][e*24+c]
__device__ float g_v  [T_TOT*INNER];   // v features
__device__ float g_cn [BE*MCEN*HDIM];  // normalized f-centers
__device__ float g_vcen[BE*MCEN*HDIM]; // raw v-centers
__device__ int   g_assign[BE*NTOK];
__device__ float g_simval[BE*NTOK];
__device__ float g_outc[BE*MCEN*HDIM];
__device__ float g_oi [T_TOT*INNER];   // scattered cluster feature per token
__device__ float g_h  [T_TOT*DD];      // x + cluster out
__device__ float g_y1 [T_TOT*DD];      // LN2(h)
__device__ float g_act[T_TOT*HID];     // gelu(fc1)

// ---------------- LayerNorm over D=768, one block per token ----------------
__global__ void __launch_bounds__(256) ln_kernel(const float* __restrict__ x,
    const float* __restrict__ w, const float* __restrict__ b, float* __restrict__ out)
{
    int t = blockIdx.x;
    const float* xr = x + (size_t)t * DD;
    float* orow = out + (size_t)t * DD;
    int tid = threadIdx.x;
    float v0 = xr[tid], v1 = xr[tid + 256], v2 = xr[tid + 512];
    float s  = v0 + v1 + v2;
    float ss = v0*v0 + v1*v1 + v2*v2;
    #pragma unroll
    for (int o = 16; o; o >>= 1) {
        s  += __shfl_xor_sync(0xffffffffu, s,  o);
        ss += __shfl_xor_sync(0xffffffffu, ss, o);
    }
    __shared__ float rs[8], rss[8];
    if ((tid & 31) == 0) { rs[tid >> 5] = s; rss[tid >> 5] = ss; }
    __syncthreads();
    float S = 0.f, SS = 0.f;
    #pragma unroll
    for (int i = 0; i < 8; i++) { S += rs[i]; SS += rss[i]; }
    float mean = S * (1.f / DD);
    float var  = SS * (1.f / DD) - mean * mean;
    float rstd = rsqrtf(var + 1e-5f);
    orow[tid]       = (v0 - mean) * rstd * w[tid]       + b[tid];
    orow[tid + 256] = (v1 - mean) * rstd * w[tid + 256] + b[tid + 256];
    orow[tid + 512] = (v2 - mean) * rstd * w[tid + 512] + b[tid + 512];
}

// ---------------- Generic register-blocked SGEMM: C = epi(A * W^T + bias) ----------------
// A: [M][K] row-major, W: [Nn][K] row-major, C: [M][Nn].
// EPI: 0 = store, 1 = exact GELU, 2 = add residual R[M][Nn]
__device__ __forceinline__ float gelu_exact(float x) {
    return 0.5f * x * (1.f + erff(x * 0.70710678118654752440f));
}

template<int BM, int BN, int BK, int TM, int TN, int EPI>
__global__ void __launch_bounds__(256) sgemm_kernel(
    const float* __restrict__ A, const float* __restrict__ W,
    const float* __restrict__ bias, const float* __restrict__ R,
    float* __restrict__ C, int M, int Nn, int K)
{
    __shared__ __align__(16) float As[BK][BM];
    __shared__ __align__(16) float Ws[BK][BN];
    const int tid = threadIdx.x;
    const int m0 = blockIdx.y * BM;
    const int n0 = blockIdx.x * BN;
    constexpr int NT = BN / TN;
    const int ty = tid / NT;
    const int tx = tid % NT;
    const int rm  = ty * TM;
    const int cnb = tx * TN;

    float acc[TM][TN];
    #pragma unroll
    for (int i = 0; i < TM; i++)
        #pragma unroll
        for (int j = 0; j < TN; j++) acc[i][j] = 0.f;

    constexpr int K4  = BK / 4;
    constexpr int AV4 = BM * BK / 4;
    constexpr int WV4 = BN * BK / 4;

    for (int k0 = 0; k0 < K; k0 += BK) {
        #pragma unroll
        for (int v = tid; v < AV4; v += 256) {
            int m = v / K4, kq = v % K4;
            float4 t = *reinterpret_cast<const float4*>(&A[(size_t)(m0 + m) * K + k0 + kq * 4]);
            As[kq*4+0][m] = t.x; As[kq*4+1][m] = t.y; As[kq*4+2][m] = t.z; As[kq*4+3][m] = t.w;
        }
        #pragma unroll
        for (int v = tid; v < WV4; v += 256) {
            int n = v / K4, kq = v % K4;
            float4 t = *reinterpret_cast<const float4*>(&W[(size_t)(n0 + n) * K + k0 + kq * 4]);
            Ws[kq*4+0][n] = t.x; Ws[kq*4+1][n] = t.y; Ws[kq*4+2][n] = t.z; Ws[kq*4+3][n] = t.w;
        }
        __syncthreads();
        #pragma unroll
        for (int kk = 0; kk < BK; kk++) {
            float a[TM], bb[TN];
            #pragma unroll
            for (int i = 0; i < TM; i++) a[i] = As[kk][rm + i];
            #pragma unroll
            for (int j = 0; j < TN; j++) bb[j] = Ws[kk][cnb + j];
            #pragma unroll
            for (int i = 0; i < TM; i++)
                #pragma unroll
                for (int j = 0; j < TN; j++)
                    acc[i][j] = fmaf(a[i], bb[j], acc[i][j]);
        }
        __syncthreads();
    }

    #pragma unroll
    for (int i = 0; i < TM; i++) {
        int row = m0 + rm + i;
        #pragma unroll
        for (int j0 = 0; j0 < TN; j0 += 4) {
            int col = n0 + cnb + j0;
            float4 bv = *reinterpret_cast<const float4*>(&bias[col]);
            float4 o;
            o.x = acc[i][j0+0] + bv.x; o.y = acc[i][j0+1] + bv.y;
            o.z = acc[i][j0+2] + bv.z; o.w = acc[i][j0+3] + bv.w;
            if (EPI == 1) {
                o.x = gelu_exact(o.x); o.y = gelu_exact(o.y);
                o.z = gelu_exact(o.z); o.w = gelu_exact(o.w);
            } else if (EPI == 2) {
                float4 rv = *reinterpret_cast<const float4*>(&R[(size_t)row * Nn + col]);
                o.x += rv.x; o.y += rv.y; o.z += rv.z; o.w += rv.w;
            }
            *reinterpret_cast<float4*>(&C[(size_t)row * Nn + col]) = o;
        }
    }
}

// ---------------- Pooling: centers (mean over 8x8 spatial block) + normalize f-centers ----
__global__ void __launch_bounds__(384) pool_kernel()
{
    int be  = blockIdx.x;            // 0..127
    int bb  = be >> 3, e = be & 7;
    int tid = threadIdx.x;           // 384 = 16 m * 24 c
    int m = tid / HDIM, c = tid % HDIM;
    int pw = m >> 2, ph = m & 3;
    float sf = 0.f, sv = 0.f;
    #pragma unroll 4
    for (int ws = 0; ws < 8; ws++) {
        #pragma unroll
        for (int hs = 0; hs < 8; hs++) {
            int n = (pw * 8 + ws) * PS + ph * 8 + hs;
            size_t idx = (size_t)(bb * NTOK + n) * INNER + e * HDIM + c;
            sf += g_f[idx];
            sv += g_v[idx];
        }
    }
    sf *= (1.f / 64.f); sv *= (1.f / 64.f);
    __shared__ float cen_s[MCEN][HDIM];
    cen_s[m][c] = sf;
    __syncthreads();
    float ssq = 0.f;
    #pragma unroll
    for (int cc = 0; cc < HDIM; cc++) { float t = cen_s[m][cc]; ssq += t * t; }
    float denom = fmaxf(sqrtf(ssq), 1e-12f);
    size_t oidx = ((size_t)be * MCEN + m) * HDIM + c;
    g_cn[oidx]   = sf / denom;
    g_vcen[oidx] = sv;
}

// ---------------- Per-token similarity + argmax assignment ----------------
__global__ void __launch_bounds__(256) assign_kernel(const float* __restrict__ alpha_p,
                                                     const float* __restrict__ beta_p)
{
    int be = blockIdx.x;
    int bb = be >> 3, e = be & 7;
    __shared__ float cns[MCEN][HDIM];
    for (int t = threadIdx.x; t < MCEN * HDIM; t += blockDim.x)
        cns[t / HDIM][t % HDIM] = g_cn[(size_t)be * MCEN * HDIM + t];
    __syncthreads();
    float alpha = *alpha_p, beta = *beta_p;
    for (int n = threadIdx.x; n < NTOK; n += blockDim.x) {
        const float* xv = g_f + (size_t)(bb * NTOK + n) * INNER + e * HDIM;
        float x[HDIM]; float ss = 0.f;
        #pragma unroll
        for (int c = 0; c < HDIM; c++) { x[c] = xv[c]; ss += x[c] * x[c]; }
        float inv = 1.f / fmaxf(sqrtf(ss), 1e-12f);
        float best = -1e30f; int bm = 0;
        #pragma unroll
        for (int m = 0; m < MCEN; m++) {
            float d = 0.f;
            #pragma unroll
            for (int c = 0; c < HDIM; c++) d = fmaf(cns[m][c], x[c], d);
            d *= inv;
            float dist = sqrtf(fmaxf(2.f - 2.f * d, 1e-12f));
            float sp = beta + alpha * expf(-dist);
            float sim = sp > 0.f ? sp : 0.2f * sp;        // leaky_relu(·, 0.2)
            if (sim > best) { best = sim; bm = m; }       // first-max, matches jnp.argmax
        }
        g_assign[(size_t)be * NTOK + n] = bm;
        g_simval[(size_t)be * NTOK + n] = best;
    }
}

// ---------------- Deterministic per-(be,m) weighted reduce to centers ----------------
__global__ void __launch_bounds__(192) outc_kernel()
{
    int m  = blockIdx.x;     // 0..15
    int be = blockIdx.y;     // 0..127
    int bb = be >> 3, e = be & 7;
    int tid = threadIdx.x;   // 192 = 24 c * 8 g
    int c = tid % HDIM, g = tid / HDIM;
    float acc = 0.f; int cnt = 0;
    for (int n = g * 128; n < g * 128 + 128; n++) {
        int a = g_assign[(size_t)be * NTOK + n];
        if (a == m) {
            float s = g_simval[(size_t)be * NTOK + n];
            acc = fmaf(s, g_v[(size_t)(bb * NTOK + n) * INNER + e * HDIM + c], acc);
            cnt++;
        }
    }
    __shared__ float pa[8][HDIM];
    __shared__ int   pc[8];
    pa[g][c] = acc;
    if (c == 0) pc[g] = cnt;
    __syncthreads();
    if (g == 0) {
        float tot = 0.f; int ct = 0;
        #pragma unroll
        for (int gg = 0; gg < 8; gg++) { tot += pa[gg][c]; ct += pc[gg]; }
        size_t oidx = ((size_t)be * MCEN + m) * HDIM + c;
        g_outc[oidx] = (tot + g_vcen[oidx]) / ((float)ct + 1.f);
    }
}

// ---------------- Scatter center features back to tokens ----------------
__global__ void __launch_bounds__(256) oi_kernel()
{
    size_t idx = (size_t)blockIdx.x * blockDim.x + threadIdx.x;
    if (idx >= (size_t)T_TOT * INNER) return;
    int t = (int)(idx / INNER), i = (int)(idx % INNER);
    int bb = t >> 10, n = t & (NTOK - 1);
    int e = i / HDIM, c = i % HDIM;
    int be = bb * HEADS + e;
    int m = g_assign[(size_t)be * NTOK + n];
    g_oi[idx] = g_simval[(size_t)be * NTOK + n] * g_outc[((size_t)be * MCEN + m) * HDIM + c];
}

// ---------------- Launch ----------------
extern "C" void kernel_launch(void* const* d_in, const int* in_sizes, int n_in,
                              void* d_out, int out_size)
{
    const float* x      = (const float*)d_in[0];
    const float* ln1_w  = (const float*)d_in[1];
    const float* ln1_b  = (const float*)d_in[2];
    const float* f_w    = (const float*)d_in[3];
    const float* f_b    = (const float*)d_in[4];
    const float* v_w    = (const float*)d_in[5];
    const float* v_b    = (const float*)d_in[6];
    const float* proj_w = (const float*)d_in[7];
    const float* proj_b = (const float*)d_in[8];
    const float* alpha  = (const float*)d_in[9];
    const float* beta   = (const float*)d_in[10];
    const float* ln2_w  = (const float*)d_in[11];
    const float* ln2_b  = (const float*)d_in[12];
    const float* fc1_w  = (const float*)d_in[13];
    const float* fc1_b  = (const float*)d_in[14];
    const float* fc2_w  = (const float*)d_in[15];
    const float* fc2_b  = (const float*)d_in[16];
    float* out = (float*)d_out;

    float *p_x1, *p_f, *p_v, *p_oi, *p_h, *p_y1, *p_act;
    cudaGetSymbolAddress((void**)&p_x1,  g_x1);
    cudaGetSymbolAddress((void**)&p_f,   g_f);
    cudaGetSymbolAddress((void**)&p_v,   g_v);
    cudaGetSymbolAddress((void**)&p_oi,  g_oi);
    cudaGetSymbolAddress((void**)&p_h,   g_h);
    cudaGetSymbolAddress((void**)&p_y1,  g_y1);
    cudaGetSymbolAddress((void**)&p_act, g_act);

    // 1) LN1
    ln_kernel<<<T_TOT, 256>>>(x, ln1_w, ln1_b, p_x1);

    // 2,3) f and v projections: [16384,768] x [192,768]^T
    {
        dim3 grid(INNER / 64, T_TOT / 128);
        sgemm_kernel<128, 64, 8, 8, 4, 0><<<grid, 256>>>(p_x1, f_w, f_b, nullptr, p_f, T_TOT, INNER, DD);
        sgemm_kernel<128, 64, 8, 8, 4, 0><<<grid, 256>>>(p_x1, v_w, v_b, nullptr, p_v, T_TOT, INNER, DD);
    }

    // 4) pooling + center normalization
    pool_kernel<<<BE, 384>>>();

    // 5) per-token assignment
    assign_kernel<<<BE, 256>>>(alpha, beta);

    // 6) weighted reduce to centers (deterministic)
    outc_kernel<<<dim3(MCEN, BE), 192>>>();

    // 7) scatter back to tokens
    {
        int total = T_TOT * INNER;
        oi_kernel<<<(total + 255) / 256, 256>>>();
    }

    // 8) proj GEMM + residual x -> h : [16384,192] x [768,192]^T + x
    sgemm_kernel<128, 128, 8, 8, 8, 2><<<dim3(DD / 128, T_TOT / 128), 256>>>(
        p_oi, proj_w, proj_b, x, p_h, T_TOT, DD, INNER);

    // 9) LN2
    ln_kernel<<<T_TOT, 256>>>(p_h, ln2_w, ln2_b, p_y1);

    // 10) fc1 + exact GELU : [16384,768] x [3072,768]^T
    sgemm_kernel<128, 128, 8, 8, 8, 1><<<dim3(HID / 128, T_TOT / 128), 256>>>(
        p_y1, fc1_w, fc1_b, nullptr, p_act, T_TOT, HID, DD);

    // 11) fc2 + residual h -> out : [16384,3072] x [768,3072]^T + h
    sgemm_kernel<128, 128, 8, 8, 8, 2><<<dim3(DD / 128, T_TOT / 128), 256>>>(
        p_act, fc2_w, fc2_b, p_h, out, T_TOT, DD, HID);
}

// round 11
// speedup vs baseline: 1.0011x; 1.0004x over previous
#include <cuda_runtime.h>
#include <cuda_bf16.h>
#include <math.h>

// ---------------- Problem constants ----------------
#define BB    16          // batch
#define PS    32
#define NTOK  1024        // PS*PS
#define DD    768
#define HEADS 8
#define HDIM  24
#define PROP  4
#define MCEN  16          // PROP*PROP
#define INNER 192         // HEADS*HDIM
#define HID   3072
#define T_TOT (BB*NTOK)   // 16384 tokens
#define BE    (BB*HEADS)  // 128

// ---------------- Scratch (device globals; no allocation APIs) ----------------
__device__ float g_x1 [T_TOT*DD];      // LN1(x)
__device__ float g_f  [T_TOT*INNER];   // f features   [t][e*24+c]
__device__ float g_v  [T_TOT*INNER];   // v features
__device__ float g_cn [BE*MCEN*HDIM];  // normalized f-centers
__device__ float g_vcen[BE*MCEN*HDIM]; // raw v-centers
__device__ int   g_assign[BE*NTOK];
__device__ float g_simval[BE*NTOK];
__device__ float g_outc[BE*MCEN*HDIM];
__device__ float g_oi [T_TOT*INNER];   // scattered cluster feature per token
__device__ float g_h  [T_TOT*DD];      // x + cluster out
__device__ float g_y1 [T_TOT*DD];      // LN2(h)
__device__ float g_act[T_TOT*HID];     // gelu(fc1)

// ---------------- LayerNorm over D=768, one block per token ----------------
__global__ void __launch_bounds__(256) ln_kernel(const float* __restrict__ x,
    const float* __restrict__ w, const float* __restrict__ b, float* __restrict__ out)
{
    int t = blockIdx.x;
    const float* xr = x + (size_t)t * DD;
    float* orow = out + (size_t)t * DD;
    int tid = threadIdx.x;
    float v0 = xr[tid], v1 = xr[tid + 256], v2 = xr[tid + 512];
    float s  = v0 + v1 + v2;
    float ss = v0*v0 + v1*v1 + v2*v2;
    #pragma unroll
    for (int o = 16; o; o >>= 1) {
        s  += __shfl_xor_sync(0xffffffffu, s,  o);
        ss += __shfl_xor_sync(0xffffffffu, ss, o);
    }
    __shared__ float rs[8], rss[8];
    if ((tid & 31) == 0) { rs[tid >> 5] = s; rss[tid >> 5] = ss; }
    __syncthreads();
    float S = 0.f, SS = 0.f;
    #pragma unroll
    for (int i = 0; i < 8; i++) { S += rs[i]; SS += rss[i]; }
    float mean = S * (1.f / DD);
    float var  = SS * (1.f / DD) - mean * mean;
    float rstd = rsqrtf(var + 1e-5f);
    orow[tid]       = (v0 - mean) * rstd * w[tid]       + b[tid];
    orow[tid + 256] = (v1 - mean) * rstd * w[tid + 256] + b[tid + 256];
    orow[tid + 512] = (v2 - mean) * rstd * w[tid + 512] + b[tid + 512];
}

// ---------------- Generic register-blocked SGEMM: C = epi(A * W^T + bias) ----------------
// A: [M][K] row-major, W: [Nn][K] row-major, C: [M][Nn].
// EPI: 0 = store, 1 = exact GELU, 2 = add residual R[M][Nn]
__device__ __forceinline__ float gelu_exact(float x) {
    return 0.5f * x * (1.f + erff(x * 0.70710678118654752440f));
}

template<int BM, int BN, int BK, int TM, int TN, int EPI>
__global__ void __launch_bounds__(256) sgemm_kernel(
    const float* __restrict__ A, const float* __restrict__ W,
    const float* __restrict__ bias, const float* __restrict__ R,
    float* __restrict__ C, int M, int Nn, int K)
{
    __shared__ __align__(16) float As[BK][BM];
    __shared__ __align__(16) float Ws[BK][BN];
    const int tid = threadIdx.x;
    const int m0 = blockIdx.y * BM;
    const int n0 = blockIdx.x * BN;
    constexpr int NT = BN / TN;
    const int ty = tid / NT;
    const int tx = tid % NT;
    const int rm  = ty * TM;
    const int cnb = tx * TN;

    float acc[TM][TN];
    #pragma unroll
    for (int i = 0; i < TM; i++)
        #pragma unroll
        for (int j = 0; j < TN; j++) acc[i][j] = 0.f;

    constexpr int K4  = BK / 4;
    constexpr int AV4 = BM * BK / 4;
    constexpr int WV4 = BN * BK / 4;

    for (int k0 = 0; k0 < K; k0 += BK) {
        #pragma unroll
        for (int v = tid; v < AV4; v += 256) {
            int m = v / K4, kq = v % K4;
            float4 t = *reinterpret_cast<const float4*>(&A[(size_t)(m0 + m) * K + k0 + kq * 4]);
            As[kq*4+0][m] = t.x; As[kq*4+1][m] = t.y; As[kq*4+2][m] = t.z; As[kq*4+3][m] = t.w;
        }
        #pragma unroll
        for (int v = tid; v < WV4; v += 256) {
            int n = v / K4, kq = v % K4;
            float4 t = *reinterpret_cast<const float4*>(&W[(size_t)(n0 + n) * K + k0 + kq * 4]);
            Ws[kq*4+0][n] = t.x; Ws[kq*4+1][n] = t.y; Ws[kq*4+2][n] = t.z; Ws[kq*4+3][n] = t.w;
        }
        __syncthreads();
        #pragma unroll
        for (int kk = 0; kk < BK; kk++) {
            float a[TM], bb[TN];
            #pragma unroll
            for (int i = 0; i < TM; i++) a[i] = As[kk][rm + i];
            #pragma unroll
            for (int j = 0; j < TN; j++) bb[j] = Ws[kk][cnb + j];
            #pragma unroll
            for (int i = 0; i < TM; i++)
                #pragma unroll
                for (int j = 0; j < TN; j++)
                    acc[i][j] = fmaf(a[i], bb[j], acc[i][j]);
        }
        __syncthreads();
    }

    #pragma unroll
    for (int i = 0; i < TM; i++) {
        int row = m0 + rm + i;
        #pragma unroll
        for (int j0 = 0; j0 < TN; j0 += 4) {
            int col = n0 + cnb + j0;
            float4 bv = *reinterpret_cast<const float4*>(&bias[col]);
            float4 o;
            o.x = acc[i][j0+0] + bv.x; o.y = acc[i][j0+1] + bv.y;
            o.z = acc[i][j0+2] + bv.z; o.w = acc[i][j0+3] + bv.w;
            if (EPI == 1) {
                o.x = gelu_exact(o.x); o.y = gelu_exact(o.y);
                o.z = gelu_exact(o.z); o.w = gelu_exact(o.w);
            } else if (EPI == 2) {
                float4 rv = *reinterpret_cast<const float4*>(&R[(size_t)row * Nn + col]);
                o.x += rv.x; o.y += rv.y; o.z += rv.z; o.w += rv.w;
            }
            *reinterpret_cast<float4*>(&C[(size_t)row * Nn + col]) = o;
        }
    }
}

// ---------------- Pooling: centers (mean over 8x8 spatial block) + normalize f-centers ----
__global__ void __launch_bounds__(384) pool_kernel()
{
    int be  = blockIdx.x;            // 0..127
    int bb  = be >> 3, e = be & 7;
    int tid = threadIdx.x;           // 384 = 16 m * 24 c
    int m = tid / HDIM, c = tid % HDIM;
    int pw = m >> 2, ph = m & 3;
    float sf = 0.f, sv = 0.f;
    #pragma unroll 4
    for (int ws = 0; ws < 8; ws++) {
        #pragma unroll
        for (int hs = 0; hs < 8; hs++) {
            int n = (pw * 8 + ws) * PS + ph * 8 + hs;
            size_t idx = (size_t)(bb * NTOK + n) * INNER + e * HDIM + c;
            sf += g_f[idx];
            sv += g_v[idx];
        }
    }
    sf *= (1.f / 64.f); sv *= (1.f / 64.f);
    __shared__ float cen_s[MCEN][HDIM];
    cen_s[m][c] = sf;
    __syncthreads();
    float ssq = 0.f;
    #pragma unroll
    for (int cc = 0; cc < HDIM; cc++) { float t = cen_s[m][cc]; ssq += t * t; }
    float denom = fmaxf(sqrtf(ssq), 1e-12f);
    size_t oidx = ((size_t)be * MCEN + m) * HDIM + c;
    g_cn[oidx]   = sf / denom;
    g_vcen[oidx] = sv;
}

// ---------------- Per-token similarity + argmax assignment ----------------
__global__ void __launch_bounds__(256) assign_kernel(const float* __restrict__ alpha_p,
                                                     const float* __restrict__ beta_p)
{
    int be = blockIdx.x;
    int bb = be >> 3, e = be & 7;
    __shared__ float cns[MCEN][HDIM];
    for (int t = threadIdx.x; t < MCEN * HDIM; t += blockDim.x)
        cns[t / HDIM][t % HDIM] = g_cn[(size_t)be * MCEN * HDIM + t];
    __syncthreads();
    float alpha = *alpha_p, beta = *beta_p;
    for (int n = threadIdx.x; n < NTOK; n += blockDim.x) {
        const float* xv = g_f + (size_t)(bb * NTOK + n) * INNER + e * HDIM;
        float x[HDIM]; float ss = 0.f;
        #pragma unroll
        for (int c = 0; c < HDIM; c++) { x[c] = xv[c]; ss += x[c] * x[c]; }
        float inv = 1.f / fmaxf(sqrtf(ss), 1e-12f);
        float best = -1e30f; int bm = 0;
        #pragma unroll
        for (int m = 0; m < MCEN; m++) {
            float d = 0.f;
            #pragma unroll
            for (int c = 0; c < HDIM; c++) d = fmaf(cns[m][c], x[c], d);
            d *= inv;
            float dist = sqrtf(fmaxf(2.f - 2.f * d, 1e-12f));
            float sp = beta + alpha * expf(-dist);
            float sim = sp > 0.f ? sp : 0.2f * sp;        // leaky_relu(·, 0.2)
            if (sim > best) { best = sim; bm = m; }       // first-max, matches jnp.argmax
        }
        g_assign[(size_t)be * NTOK + n] = bm;
        g_simval[(size_t)be * NTOK + n] = best;
    }
}

// ---------------- Deterministic per-(be,m) weighted reduce to centers ----------------
__global__ void __launch_bounds__(192) outc_kernel()
{
    int m  = blockIdx.x;     // 0..15
    int be = blockIdx.y;     // 0..127
    int bb = be >> 3, e = be & 7;
    int tid = threadIdx.x;   // 192 = 24 c * 8 g
    int c = tid % HDIM, g = tid / HDIM;
    float acc = 0.f; int cnt = 0;
    for (int n = g * 128; n < g * 128 + 128; n++) {
        int a = g_assign[(size_t)be * NTOK + n];
        if (a == m) {
            float s = g_simval[(size_t)be * NTOK + n];
            acc = fmaf(s, g_v[(size_t)(bb * NTOK + n) * INNER + e * HDIM + c], acc);
            cnt++;
        }
    }
    __shared__ float pa[8][HDIM];
    __shared__ int   pc[8];
    pa[g][c] = acc;
    if (c == 0) pc[g] = cnt;
    __syncthreads();
    if (g == 0) {
        float tot = 0.f; int ct = 0;
        #pragma unroll
        for (int gg = 0; gg < 8; gg++) { tot += pa[gg][c]; ct += pc[gg]; }
        size_t oidx = ((size_t)be * MCEN + m) * HDIM + c;
        g_outc[oidx] = (tot + g_vcen[oidx]) / ((float)ct + 1.f);
    }
}

// ---------------- Scatter center features back to tokens ----------------
__global__ void __launch_bounds__(256) oi_kernel()
{
    size_t idx = (size_t)blockIdx.x * blockDim.x + threadIdx.x;
    if (idx >= (size_t)T_TOT * INNER) return;
    int t = (int)(idx / INNER), i = (int)(idx % INNER);
    int bb = t >> 10, n = t & (NTOK - 1);
    int e = i / HDIM, c = i % HDIM;
    int be = bb * HEADS + e;
    int m = g_assign[(size_t)be * NTOK + n];
    g_oi[idx] = g_simval[(size_t)be * NTOK + n] * g_outc[((size_t)be * MCEN + m) * HDIM + c];
}

// ---------------- Launch ----------------
extern "C" void kernel_launch(void* const* d_in, const int* in_sizes, int n_in,
                              void* d_out, int out_size)
{
    const float* x      = (const float*)d_in[0];
    const float* ln1_w  = (const float*)d_in[1];
    const float* ln1_b  = (const float*)d_in[2];
    const float* f_w    = (const float*)d_in[3];
    const float* f_b    = (const float*)d_in[4];
    const float* v_w    = (const float*)d_in[5];
    const float* v_b    = (const float*)d_in[6];
    const float* proj_w = (const float*)d_in[7];
    const float* proj_b = (const float*)d_in[8];
    const float* alpha  = (const float*)d_in[9];
    const float* beta   = (const float*)d_in[10];
    const float* ln2_w  = (const float*)d_in[11];
    const float* ln2_b  = (const float*)d_in[12];
    const float* fc1_w  = (const float*)d_in[13];
    const float* fc1_b  = (const float*)d_in[14];
    const float* fc2_w  = (const float*)d_in[15];
    const float* fc2_b  = (const float*)d_in[16];
    float* out = (float*)d_out;

    float *p_x1, *p_f, *p_v, *p_oi, *p_h, *p_y1, *p_act;
    cudaGetSymbolAddress((void**)&p_x1,  g_x1);
    cudaGetSymbolAddress((void**)&p_f,   g_f);
    cudaGetSymbolAddress((void**)&p_v,   g_v);
    cudaGetSymbolAddress((void**)&p_oi,  g_oi);
    cudaGetSymbolAddress((void**)&p_h,   g_h);
    cudaGetSymbolAddress((void**)&p_y1,  g_y1);
    cudaGetSymbolAddress((void**)&p_act, g_act);

    // 1) LN1
    ln_kernel<<<T_TOT, 256>>>(x, ln1_w, ln1_b, p_x1);

    // 2,3) f and v projections: [16384,768] x [192,768]^T
    {
        dim3 grid(INNER / 64, T_TOT / 128);
        sgemm_kernel<128, 64, 8, 8, 4, 0><<<grid, 256>>>(p_x1, f_w, f_b, nullptr, p_f, T_TOT, INNER, DD);
        sgemm_kernel<128, 64, 8, 8, 4, 0><<<grid, 256>>>(p_x1, v_w, v_b, nullptr, p_v, T_TOT, INNER, DD);
    }

    // 4) pooling + center normalization
    pool_kernel<<<BE, 384>>>();

    // 5) per-token assignment
    assign_kernel<<<BE, 256>>>(alpha, beta);

    // 6) weighted reduce to centers (deterministic)
    outc_kernel<<<dim3(MCEN, BE), 192>>>();

    // 7) scatter back to tokens
    {
        int total = T_TOT * INNER;
        oi_kernel<<<(total + 255) / 256, 256>>>();
    }

    // 8) proj GEMM + residual x -> h : [16384,192] x [768,192]^T + x
    sgemm_kernel<128, 128, 8, 8, 8, 2><<<dim3(DD / 128, T_TOT / 128), 256>>>(
        p_oi, proj_w, proj_b, x, p_h, T_TOT, DD, INNER);

    // 9) LN2
    ln_kernel<<<T_TOT, 256>>>(p_h, ln2_w, ln2_b, p_y1);

    // 10) fc1 + exact GELU : [16384,768] x [3072,768]^T
    sgemm_kernel<128, 128, 8, 8, 8, 1><<<dim3(HID / 128, T_TOT / 128), 256>>>(
        p_y1, fc1_w, fc1_b, nullptr, p_act, T_TOT, HID, DD);

    // 11) fc2 + residual h -> out : [16384,3072] x [768,3072]^T + h
    sgemm_kernel<128, 128, 8, 8, 8, 2><<<dim3(DD / 128, T_TOT / 128), 256>>>(
        p_act, fc2_w, fc2_b, p_h, out, T_TOT, DD, HID);
}

// round 14
// speedup vs baseline: 2.7566x; 2.7535x over previous
#include <cuda_runtime.h>
#include <math.h>
#include <stdint.h>

// ---------------- Problem constants ----------------
#define BB    16          // batch
#define PS    32
#define NTOK  1024        // PS*PS
#define DD    768
#define HEADS 8
#define HDIM  24
#define MCEN  16
#define INNER 192         // HEADS*HDIM
#define HID   3072
#define T_TOT (BB*NTOK)   // 16384 tokens
#define BE    (BB*HEADS)  // 128

// ---------------- Scratch (device globals; no allocation APIs) ----------------
__device__ float g_x1 [T_TOT*DD];
__device__ float g_f  [T_TOT*INNER];
__device__ float g_v  [T_TOT*INNER];
__device__ float g_cn [BE*MCEN*HDIM];
__device__ float g_vcen[BE*MCEN*HDIM];
__device__ int   g_assign[BE*NTOK];
__device__ float g_simval[BE*NTOK];
__device__ float g_outc[BE*MCEN*HDIM];
__device__ float g_oi [T_TOT*INNER];
__device__ float g_h  [T_TOT*DD];
__device__ float g_y1 [T_TOT*DD];
__device__ float g_act[T_TOT*HID];

// ================= helpers =================
__device__ __forceinline__ uint32_t f2tf32(float x) {
    uint32_t r;
    asm("cvt.rna.tf32.f32 %0, %1;" : "=r"(r) : "f"(x));
    return r;
}
__device__ __forceinline__ float tf32_round(float x) {
    return __uint_as_float(f2tf32(x));
}
__device__ __forceinline__ float gelu_exact(float x) {
    return 0.5f * x * (1.f + erff(x * 0.70710678118654752440f));
}

// mma.sync m16n8k8 tf32: D += A*B (row.col), fp32 accumulate
__device__ __forceinline__ void mma_tf32(float* d, const uint32_t* a, const uint32_t* b) {
    asm volatile(
        "mma.sync.aligned.m16n8k8.row.col.f32.tf32.tf32.f32 "
        "{%0,%1,%2,%3}, {%4,%5,%6,%7}, {%8,%9}, {%0,%1,%2,%3};"
        : "+f"(d[0]), "+f"(d[1]), "+f"(d[2]), "+f"(d[3])
        : "r"(a[0]), "r"(a[1]), "r"(a[2]), "r"(a[3]), "r"(b[0]), "r"(b[1]));
}

#define CP_ASYNC16(dst32, src) \
    asm volatile("cp.async.cg.shared.global [%0], [%1], 16;" :: "r"(dst32), "l"(src))
#define CP_COMMIT() asm volatile("cp.async.commit_group;" ::: "memory")
#define CP_WAIT1()  asm volatile("cp.async.wait_group 1;" ::: "memory")
#define CP_WAIT0()  asm volatile("cp.async.wait_group 0;" ::: "memory")

// ================= tensor-core GEMM (mma.sync tf32) =================
// C[M][Nn] = epi(A[M][K] * W[Nn][K]^T + bias).  BM=128, BK=32, 256 threads.
// Warp grid 2(m) x 4(n); per-warp tile 64 x (BN/4).
// EPI: 0=store, 1=exact GELU, 2=add residual R.
// SPLIT: 3-term tf32 split (fp32-grade), synchronous single-buffer loads.
template<int BN, int EPI, bool SPLIT>
__global__ void __launch_bounds__(256) mma_gemm(
    const float* __restrict__ A, const float* __restrict__ W,
    const float* __restrict__ bias, const float* __restrict__ R,
    float* __restrict__ C, int M, int Nn, int K)
{
    extern __shared__ float sm[];
    constexpr int LDSR  = 36;            // padded row stride (floats): conflict-free frags
    constexpr int ABUF  = 128 * LDSR;
    constexpr int BBUF  = BN * LDSR;
    constexpr int NT    = BN / 32;       // n-tiles (8 cols) per warp
    constexpr int A4    = 128 * 8;       // float4 count for A chunk
    constexpr int TOT4  = A4 + BN * 8;

    const int tid  = threadIdx.x;
    const int lane = tid & 31, warp = tid >> 5;
    const int wm = warp & 1, wn = warp >> 1;
    const int g = lane >> 2, t = lane & 3;
    const int m0 = blockIdx.y * 128;
    const int n0 = blockIdx.x * BN;
    const int NC = K / 32;

    float acc[4][NT][4];
    #pragma unroll
    for (int mi = 0; mi < 4; mi++)
        #pragma unroll
        for (int ni = 0; ni < NT; ni++)
            #pragma unroll
            for (int r = 0; r < 4; r++) acc[mi][ni][r] = 0.f;

    if (!SPLIT) {
        // ---- double-buffered cp.async pipeline ----
        auto load_chunk = [&](int c, int p) {
            float* dst = sm + p * (ABUF + BBUF);
            const int k0 = c * 32;
            #pragma unroll
            for (int v = tid; v < TOT4; v += 256) {
                const float* src; float* d;
                if (v < A4) {
                    int row = v >> 3, q = v & 7;
                    src = A + (size_t)(m0 + row) * K + k0 + q * 4;
                    d   = dst + row * LDSR + q * 4;
                } else {
                    int u = v - A4; int row = u >> 3, q = u & 7;
                    src = W + (size_t)(n0 + row) * K + k0 + q * 4;
                    d   = dst + ABUF + row * LDSR + q * 4;
                }
                CP_ASYNC16((uint32_t)__cvta_generic_to_shared(d), src);
            }
            CP_COMMIT();
        };

        load_chunk(0, 0);
        for (int c = 0; c < NC; c++) {
            const int p = c & 1;
            if (c + 1 < NC) { load_chunk(c + 1, p ^ 1); CP_WAIT1(); }
            else            { CP_WAIT0(); }
            __syncthreads();

            const float* As = sm + p * (ABUF + BBUF);
            const float* Ws = As + ABUF;
            #pragma unroll
            for (int kk = 0; kk < 32; kk += 8) {
                uint32_t a[4][4], b[NT][2];
                #pragma unroll
                for (int mi = 0; mi < 4; mi++) {
                    const int r0 = wm * 64 + mi * 16 + g;
                    a[mi][0] = f2tf32(As[r0 * LDSR + kk + t]);
                    a[mi][1] = f2tf32(As[(r0 + 8) * LDSR + kk + t]);
                    a[mi][2] = f2tf32(As[r0 * LDSR + kk + t + 4]);
                    a[mi][3] = f2tf32(As[(r0 + 8) * LDSR + kk + t + 4]);
                }
                #pragma unroll
                for (int ni = 0; ni < NT; ni++) {
                    const int c0 = wn * NT * 8 + ni * 8 + g;
                    b[ni][0] = f2tf32(Ws[c0 * LDSR + kk + t]);
                    b[ni][1] = f2tf32(Ws[c0 * LDSR + kk + t + 4]);
                }
                #pragma unroll
                for (int mi = 0; mi < 4; mi++)
                    #pragma unroll
                    for (int ni = 0; ni < NT; ni++)
                        mma_tf32(acc[mi][ni], a[mi], b[ni]);
            }
            __syncthreads();
        }
    } else {
        // ---- split-tf32, synchronous single buffer ----
        float* Ahi = sm;
        float* Alo = sm + ABUF;
        float* Whi = sm + 2 * ABUF;
        float* Wlo = Whi + BBUF;
        for (int c = 0; c < NC; c++) {
            const int k0 = c * 32;
            __syncthreads();
            #pragma unroll
            for (int v = tid; v < TOT4; v += 256) {
                const float* src; float *dh, *dl;
                if (v < A4) {
                    int row = v >> 3, q = v & 7;
                    src = A + (size_t)(m0 + row) * K + k0 + q * 4;
                    dh = Ahi + row * LDSR + q * 4; dl = Alo + row * LDSR + q * 4;
                } else {
                    int u = v - A4; int row = u >> 3, q = u & 7;
                    src = W + (size_t)(n0 + row) * K + k0 + q * 4;
                    dh = Whi + row * LDSR + q * 4; dl = Wlo + row * LDSR + q * 4;
                }
                float4 tv = *(const float4*)src;
                float4 hi, lo;
                hi.x = tf32_round(tv.x); lo.x = tf32_round(tv.x - hi.x);
                hi.y = tf32_round(tv.y); lo.y = tf32_round(tv.y - hi.y);
                hi.z = tf32_round(tv.z); lo.z = tf32_round(tv.z - hi.z);
                hi.w = tf32_round(tv.w); lo.w = tf32_round(tv.w - hi.w);
                *(float4*)dh = hi; *(float4*)dl = lo;
            }
            __syncthreads();
            #pragma unroll
            for (int kk = 0; kk < 32; kk += 8) {
                uint32_t ah[4][4], al[4][4], bh[NT][2], bl[NT][2];
                #pragma unroll
                for (int mi = 0; mi < 4; mi++) {
                    const int r0 = wm * 64 + mi * 16 + g;
                    ah[mi][0] = __float_as_uint(Ahi[r0 * LDSR + kk + t]);
                    ah[mi][1] = __float_as_uint(Ahi[(r0 + 8) * LDSR + kk + t]);
                    ah[mi][2] = __float_as_uint(Ahi[r0 * LDSR + kk + t + 4]);
                    ah[mi][3] = __float_as_uint(Ahi[(r0 + 8) * LDSR + kk + t + 4]);
                    al[mi][0] = __float_as_uint(Alo[r0 * LDSR + kk + t]);
                    al[mi][1] = __float_as_uint(Alo[(r0 + 8) * LDSR + kk + t]);
                    al[mi][2] = __float_as_uint(Alo[r0 * LDSR + kk + t + 4]);
                    al[mi][3] = __float_as_uint(Alo[(r0 + 8) * LDSR + kk + t + 4]);
                }
                #pragma unroll
                for (int ni = 0; ni < NT; ni++) {
                    const int c0 = wn * NT * 8 + ni * 8 + g;
                    bh[ni][0] = __float_as_uint(Whi[c0 * LDSR + kk + t]);
                    bh[ni][1] = __float_as_uint(Whi[c0 * LDSR + kk + t + 4]);
                    bl[ni][0] = __float_as_uint(Wlo[c0 * LDSR + kk + t]);
                    bl[ni][1] = __float_as_uint(Wlo[c0 * LDSR + kk + t + 4]);
                }
                #pragma unroll
                for (int mi = 0; mi < 4; mi++)
                    #pragma unroll
                    for (int ni = 0; ni < NT; ni++) {
                        mma_tf32(acc[mi][ni], ah[mi], bh[ni]);
                        mma_tf32(acc[mi][ni], ah[mi], bl[ni]);
                        mma_tf32(acc[mi][ni], al[mi], bh[ni]);
                    }
            }
        }
    }

    // ---- epilogue ----
    #pragma unroll
    for (int mi = 0; mi < 4; mi++) {
        const int row = m0 + wm * 64 + mi * 16 + g;
        #pragma unroll
        for (int ni = 0; ni < NT; ni++) {
            const int col = n0 + wn * NT * 8 + ni * 8 + 2 * t;
            float2 bv = *(const float2*)&bias[col];
            float o0 = acc[mi][ni][0] + bv.x;
            float o1 = acc[mi][ni][1] + bv.y;
            float o2 = acc[mi][ni][2] + bv.x;
            float o3 = acc[mi][ni][3] + bv.y;
            if (EPI == 1) {
                o0 = gelu_exact(o0); o1 = gelu_exact(o1);
                o2 = gelu_exact(o2); o3 = gelu_exact(o3);
            } else if (EPI == 2) {
                float2 r0 = *(const float2*)&R[(size_t)row * Nn + col];
                float2 r1 = *(const float2*)&R[(size_t)(row + 8) * Nn + col];
                o0 += r0.x; o1 += r0.y; o2 += r1.x; o3 += r1.y;
            }
            float2 s0 = make_float2(o0, o1), s1 = make_float2(o2, o3);
            *(float2*)&C[(size_t)row * Nn + col] = s0;
            *(float2*)&C[(size_t)(row + 8) * Nn + col] = s1;
        }
    }
}

// ---------------- LayerNorm over D=768, one block per token ----------------
__global__ void __launch_bounds__(256) ln_kernel(const float* __restrict__ x,
    const float* __restrict__ w, const float* __restrict__ b, float* __restrict__ out)
{
    int t = blockIdx.x;
    const float* xr = x + (size_t)t * DD;
    float* orow = out + (size_t)t * DD;
    int tid = threadIdx.x;
    float v0 = xr[tid], v1 = xr[tid + 256], v2 = xr[tid + 512];
    float s  = v0 + v1 + v2;
    float ss = v0*v0 + v1*v1 + v2*v2;
    #pragma unroll
    for (int o = 16; o; o >>= 1) {
        s  += __shfl_xor_sync(0xffffffffu, s,  o);
        ss += __shfl_xor_sync(0xffffffffu, ss, o);
    }
    __shared__ float rs[8], rss[8];
    if ((tid & 31) == 0) { rs[tid >> 5] = s; rss[tid >> 5] = ss; }
    __syncthreads();
    float S = 0.f, SS = 0.f;
    #pragma unroll
    for (int i = 0; i < 8; i++) { S += rs[i]; SS += rss[i]; }
    float mean = S * (1.f / DD);
    float var  = SS * (1.f / DD) - mean * mean;
    float rstd = rsqrtf(var + 1e-5f);
    orow[tid]       = (v0 - mean) * rstd * w[tid]       + b[tid];
    orow[tid + 256] = (v1 - mean) * rstd * w[tid + 256] + b[tid + 256];
    orow[tid + 512] = (v2 - mean) * rstd * w[tid + 512] + b[tid + 512];
}

// ---------------- Pooling: centers + normalize f-centers ----------------
__global__ void __launch_bounds__(384) pool_kernel()
{
    int be  = blockIdx.x;
    int bb  = be >> 3, e = be & 7;
    int tid = threadIdx.x;           // 384 = 16 m * 24 c
    int m = tid / HDIM, c = tid % HDIM;
    int pw = m >> 2, ph = m & 3;
    float sf = 0.f, sv = 0.f;
    #pragma unroll 4
    for (int ws = 0; ws < 8; ws++) {
        #pragma unroll
        for (int hs = 0; hs < 8; hs++) {
            int n = (pw * 8 + ws) * PS + ph * 8 + hs;
            size_t idx = (size_t)(bb * NTOK + n) * INNER + e * HDIM + c;
            sf += g_f[idx];
            sv += g_v[idx];
        }
    }
    sf *= (1.f / 64.f); sv *= (1.f / 64.f);
    __shared__ float cen_s[MCEN][HDIM];
    cen_s[m][c] = sf;
    __syncthreads();
    float ssq = 0.f;
    #pragma unroll
    for (int cc = 0; cc < HDIM; cc++) { float t = cen_s[m][cc]; ssq += t * t; }
    float denom = fmaxf(sqrtf(ssq), 1e-12f);
    size_t oidx = ((size_t)be * MCEN + m) * HDIM + c;
    g_cn[oidx]   = sf / denom;
    g_vcen[oidx] = sv;
}

// ---------------- Per-token similarity + argmax assignment ----------------
__global__ void __launch_bounds__(256) assign_kernel(const float* __restrict__ alpha_p,
                                                     const float* __restrict__ beta_p)
{
    int be = blockIdx.x;
    int bb = be >> 3, e = be & 7;
    __shared__ float cns[MCEN][HDIM];
    for (int t = threadIdx.x; t < MCEN * HDIM; t += blockDim.x)
        cns[t / HDIM][t % HDIM] = g_cn[(size_t)be * MCEN * HDIM + t];
    __syncthreads();
    float alpha = *alpha_p, beta = *beta_p;
    for (int n = threadIdx.x; n < NTOK; n += blockDim.x) {
        const float* xv = g_f + (size_t)(bb * NTOK + n) * INNER + e * HDIM;
        float x[HDIM]; float ss = 0.f;
        #pragma unroll
        for (int c = 0; c < HDIM; c++) { x[c] = xv[c]; ss += x[c] * x[c]; }
        float inv = 1.f / fmaxf(sqrtf(ss), 1e-12f);
        float best = -1e30f; int bm = 0;
        #pragma unroll
        for (int m = 0; m < MCEN; m++) {
            float d = 0.f;
            #pragma unroll
            for (int c = 0; c < HDIM; c++) d = fmaf(cns[m][c], x[c], d);
            d *= inv;
            float dist = sqrtf(fmaxf(2.f - 2.f * d, 1e-12f));
            float sp = beta + alpha * expf(-dist);
            float sim = sp > 0.f ? sp : 0.2f * sp;
            if (sim > best) { best = sim; bm = m; }
        }
        g_assign[(size_t)be * NTOK + n] = bm;
        g_simval[(size_t)be * NTOK + n] = best;
    }
}

// ---------------- Deterministic per-(be,m) weighted reduce to centers ----------------
__global__ void __launch_bounds__(192) outc_kernel()
{
    int m  = blockIdx.x;
    int be = blockIdx.y;
    int bb = be >> 3, e = be & 7;
    int tid = threadIdx.x;   // 192 = 24 c * 8 g
    int c = tid % HDIM, g = tid / HDIM;
    float acc = 0.f; int cnt = 0;
    for (int n = g * 128; n < g * 128 + 128; n++) {
        int a = g_assign[(size_t)be * NTOK + n];
        if (a == m) {
            float s = g_simval[(size_t)be * NTOK + n];
            acc = fmaf(s, g_v[(size_t)(bb * NTOK + n) * INNER + e * HDIM + c], acc);
            cnt++;
        }
    }
    __shared__ float pa[8][HDIM];
    __shared__ int   pc[8];
    pa[g][c] = acc;
    if (c == 0) pc[g] = cnt;
    __syncthreads();
    if (g == 0) {
        float tot = 0.f; int ct = 0;
        #pragma unroll
        for (int gg = 0; gg < 8; gg++) { tot += pa[gg][c]; ct += pc[gg]; }
        size_t oidx = ((size_t)be * MCEN + m) * HDIM + c;
        g_outc[oidx] = (tot + g_vcen[oidx]) / ((float)ct + 1.f);
    }
}

// ---------------- Scatter center features back to tokens ----------------
__global__ void __launch_bounds__(256) oi_kernel()
{
    size_t idx = (size_t)blockIdx.x * blockDim.x + threadIdx.x;
    if (idx >= (size_t)T_TOT * INNER) return;
    int t = (int)(idx / INNER), i = (int)(idx % INNER);
    int bb = t >> 10, n = t & (NTOK - 1);
    int e = i / HDIM, c = i % HDIM;
    int be = bb * HEADS + e;
    int m = g_assign[(size_t)be * NTOK + n];
    g_oi[idx] = g_simval[(size_t)be * NTOK + n] * g_outc[((size_t)be * MCEN + m) * HDIM + c];
}

// ---------------- Launch ----------------
extern "C" void kernel_launch(void* const* d_in, const int* in_sizes, int n_in,
                              void* d_out, int out_size)
{
    const float* x      = (const float*)d_in[0];
    const float* ln1_w  = (const float*)d_in[1];
    const float* ln1_b  = (const float*)d_in[2];
    const float* f_w    = (const float*)d_in[3];
    const float* f_b    = (const float*)d_in[4];
    const float* v_w    = (const float*)d_in[5];
    const float* v_b    = (const float*)d_in[6];
    const float* proj_w = (const float*)d_in[7];
    const float* proj_b = (const float*)d_in[8];
    const float* alpha  = (const float*)d_in[9];
    const float* beta   = (const float*)d_in[10];
    const float* ln2_w  = (const float*)d_in[11];
    const float* ln2_b  = (const float*)d_in[12];
    const float* fc1_w  = (const float*)d_in[13];
    const float* fc1_b  = (const float*)d_in[14];
    const float* fc2_w  = (const float*)d_in[15];
    const float* fc2_b  = (const float*)d_in[16];
    float* out = (float*)d_out;

    float *p_x1, *p_f, *p_v, *p_oi, *p_h, *p_y1, *p_act;
    cudaGetSymbolAddress((void**)&p_x1,  g_x1);
    cudaGetSymbolAddress((void**)&p_f,   g_f);
    cudaGetSymbolAddress((void**)&p_v,   g_v);
    cudaGetSymbolAddress((void**)&p_oi,  g_oi);
    cudaGetSymbolAddress((void**)&p_h,   g_h);
    cudaGetSymbolAddress((void**)&p_y1,  g_y1);
    cudaGetSymbolAddress((void**)&p_act, g_act);

    // dynamic SMEM (floats -> bytes):
    const int SM_BN128 = 2 * (128 * 36 + 128 * 36) * 4;  // 73728
    const int SM_BN64  = 2 * (128 * 36 +  64 * 36) * 4;  // 55296
    const int SM_SPLIT = (2 * 128 * 36 + 2 * 64 * 36) * 4; // 55296
    cudaFuncSetAttribute(mma_gemm<64, 0, true >, cudaFuncAttributeMaxDynamicSharedMemorySize, SM_SPLIT);
    cudaFuncSetAttribute(mma_gemm<64, 0, false>, cudaFuncAttributeMaxDynamicSharedMemorySize, SM_BN64);
    cudaFuncSetAttribute(mma_gemm<128, 1, false>, cudaFuncAttributeMaxDynamicSharedMemorySize, SM_BN128);
    cudaFuncSetAttribute(mma_gemm<128, 2, false>, cudaFuncAttributeMaxDynamicSharedMemorySize, SM_BN128);

    // 1) LN1
    ln_kernel<<<T_TOT, 256>>>(x, ln1_w, ln1_b, p_x1);

    // 2) f projection (split-tf32, fp32-grade: feeds argmax assignment)
    mma_gemm<64, 0, true ><<<dim3(INNER / 64, T_TOT / 128), 256, SM_SPLIT>>>(
        p_x1, f_w, f_b, nullptr, p_f, T_TOT, INNER, DD);
    // 3) v projection (plain tf32)
    mma_gemm<64, 0, false><<<dim3(INNER / 64, T_TOT / 128), 256, SM_BN64>>>(
        p_x1, v_w, v_b, nullptr, p_v, T_TOT, INNER, DD);

    // 4) pooling + center normalization
    pool_kernel<<<BE, 384>>>();
    // 5) per-token assignment
    assign_kernel<<<BE, 256>>>(alpha, beta);
    // 6) weighted reduce to centers (deterministic)
    outc_kernel<<<dim3(MCEN, BE), 192>>>();
    // 7) scatter back to tokens
    oi_kernel<<<(T_TOT * INNER + 255) / 256, 256>>>();

    // 8) proj + residual x -> h
    mma_gemm<128, 2, false><<<dim3(DD / 128, T_TOT / 128), 256, SM_BN128>>>(
        p_oi, proj_w, proj_b, x, p_h, T_TOT, DD, INNER);

    // 9) LN2
    ln_kernel<<<T_TOT, 256>>>(p_h, ln2_w, ln2_b, p_y1);

    // 10) fc1 + exact GELU
    mma_gemm<128, 1, false><<<dim3(HID / 128, T_TOT / 128), 256, SM_BN128>>>(
        p_y1, fc1_w, fc1_b, nullptr, p_act, T_TOT, HID, DD);

    // 11) fc2 + residual h -> out
    mma_gemm<128, 2, false><<<dim3(DD / 128, T_TOT / 128), 256, SM_BN128>>>(
        p_act, fc2_w, fc2_b, p_h, out, T_TOT, DD, HID);
}

// round 15
// speedup vs baseline: 4.6620x; 1.6912x over previous
#include <cuda_runtime.h>
#include <cuda_fp16.h>
#include <math.h>
#include <stdint.h>

// ---------------- Problem constants ----------------
#define BB    16
#define PS    32
#define NTOK  1024
#define DD    768
#define HEADS 8
#define HDIM  24
#define MCEN  16
#define INNER 192
#define HID   3072
#define T_TOT (BB*NTOK)   // 16384
#define BE    (BB*HEADS)  // 128

// ---------------- Scratch (device globals) ----------------
__device__ float  g_x1 [T_TOT*DD];      // LN1(x) fp32 (for f split GEMM)
__device__ __half g_x1h[T_TOT*DD];      // LN1(x) fp16 (for v GEMM)
__device__ float  g_f  [T_TOT*INNER];
__device__ float  g_v  [T_TOT*INNER];
__device__ float  g_cn [BE*MCEN*HDIM];
__device__ float  g_vcen[BE*MCEN*HDIM];
__device__ int    g_assign[BE*NTOK];
__device__ float  g_simval[BE*NTOK];
__device__ float  g_outc[BE*MCEN*HDIM];
__device__ __half g_oih[T_TOT*INNER];
__device__ float  g_h  [T_TOT*DD];
__device__ __half g_y1h[T_TOT*DD];
__device__ __half g_acth[T_TOT*HID];
// fp16 weights (converted per launch)
__device__ __half g_vwh [INNER*DD];
__device__ __half g_pwh [DD*INNER];
__device__ __half g_f1wh[HID*DD];
__device__ __half g_f2wh[DD*HID];

// ================= helpers =================
__device__ __forceinline__ uint32_t f2tf32(float x) {
    uint32_t r;
    asm("cvt.rna.tf32.f32 %0, %1;" : "=r"(r) : "f"(x));
    return r;
}
__device__ __forceinline__ float tf32_round(float x) { return __uint_as_float(f2tf32(x)); }
__device__ __forceinline__ float gelu_exact(float x) {
    return 0.5f * x * (1.f + erff(x * 0.70710678118654752440f));
}

__device__ __forceinline__ void mma_tf32(float* d, const uint32_t* a, const uint32_t* b) {
    asm volatile(
        "mma.sync.aligned.m16n8k8.row.col.f32.tf32.tf32.f32 "
        "{%0,%1,%2,%3}, {%4,%5,%6,%7}, {%8,%9}, {%0,%1,%2,%3};"
        : "+f"(d[0]), "+f"(d[1]), "+f"(d[2]), "+f"(d[3])
        : "r"(a[0]), "r"(a[1]), "r"(a[2]), "r"(a[3]), "r"(b[0]), "r"(b[1]));
}
__device__ __forceinline__ void mma_f16(float* d, const uint32_t* a, const uint32_t* b) {
    asm volatile(
        "mma.sync.aligned.m16n8k16.row.col.f32.f16.f16.f32 "
        "{%0,%1,%2,%3}, {%4,%5,%6,%7}, {%8,%9}, {%0,%1,%2,%3};"
        : "+f"(d[0]), "+f"(d[1]), "+f"(d[2]), "+f"(d[3])
        : "r"(a[0]), "r"(a[1]), "r"(a[2]), "r"(a[3]), "r"(b[0]), "r"(b[1]));
}

#define CP_ASYNC16(dst32, src) \
    asm volatile("cp.async.cg.shared.global [%0], [%1], 16;" :: "r"(dst32), "l"(src))
#define CP_COMMIT() asm volatile("cp.async.commit_group;" ::: "memory")
#define CP_WAIT1()  asm volatile("cp.async.wait_group 1;" ::: "memory")
#define CP_WAIT0()  asm volatile("cp.async.wait_group 0;" ::: "memory")

// ================= fp16 tensor-core GEMM =================
// C[M][Nn] = epi(A[M][K] * W[Nn][K]^T + bias). A,W fp16. BM=128, BK=32, 256 thr.
// Warp grid 2(m) x 4(n); per-warp 64 x (BN/4). EPI: 0=store,1=GELU,2=+residual.
// OUTH: store fp16 (for fc1 activations).
template<int BN, int EPI, bool OUTH>
__global__ void __launch_bounds__(256) hgemm(
    const __half* __restrict__ A, const __half* __restrict__ W,
    const float* __restrict__ bias, const float* __restrict__ R,
    void* __restrict__ Cv, int M, int Nn, int K)
{
    extern __shared__ __half smh[];
    constexpr int LDSR = 40;             // halves; 80B stride -> conflict-free frags
    constexpr int ABUF = 128 * LDSR;
    constexpr int BBUF = BN * LDSR;
    constexpr int NT   = BN / 32;
    constexpr int AU   = 128 * 4;        // 16B units for A chunk (128 rows x 64B)
    constexpr int TOTU = AU + BN * 4;

    const int tid  = threadIdx.x;
    const int lane = tid & 31, warp = tid >> 5;
    const int wm = warp & 1, wn = warp >> 1;
    const int g = lane >> 2, t = lane & 3;
    const int m0 = blockIdx.y * 128;
    const int n0 = blockIdx.x * BN;
    const int NC = K / 32;

    float acc[4][NT][4];
    #pragma unroll
    for (int mi = 0; mi < 4; mi++)
        #pragma unroll
        for (int ni = 0; ni < NT; ni++)
            #pragma unroll
            for (int r = 0; r < 4; r++) acc[mi][ni][r] = 0.f;

    auto load_chunk = [&](int c, int p) {
        __half* dst = smh + p * (ABUF + BBUF);
        const int k0 = c * 32;
        #pragma unroll
        for (int v = tid; v < TOTU; v += 256) {
            const __half* src; __half* d;
            int row = v >> 2, q = v & 3;
            if (row < 128) {
                src = A + (size_t)(m0 + row) * K + k0 + q * 8;
                d   = dst + row * LDSR + q * 8;
            } else {
                int r2 = row - 128;
                src = W + (size_t)(n0 + r2) * K + k0 + q * 8;
                d   = dst + ABUF + r2 * LDSR + q * 8;
            }
            CP_ASYNC16((uint32_t)__cvta_generic_to_shared(d), src);
        }
        CP_COMMIT();
    };

    load_chunk(0, 0);
    for (int c = 0; c < NC; c++) {
        const int p = c & 1;
        if (c + 1 < NC) { load_chunk(c + 1, p ^ 1); CP_WAIT1(); }
        else            { CP_WAIT0(); }
        __syncthreads();

        const __half* As = smh + p * (ABUF + BBUF);
        const __half* Ws = As + ABUF;
        #pragma unroll
        for (int kk = 0; kk < 32; kk += 16) {
            uint32_t a[4][4], b[NT][2];
            #pragma unroll
            for (int mi = 0; mi < 4; mi++) {
                const int r0 = wm * 64 + mi * 16 + g;
                a[mi][0] = *(const uint32_t*)&As[r0 * LDSR + kk + 2 * t];
                a[mi][1] = *(const uint32_t*)&As[(r0 + 8) * LDSR + kk + 2 * t];
                a[mi][2] = *(const uint32_t*)&As[r0 * LDSR + kk + 8 + 2 * t];
                a[mi][3] = *(const uint32_t*)&As[(r0 + 8) * LDSR + kk + 8 + 2 * t];
            }
            #pragma unroll
            for (int ni = 0; ni < NT; ni++) {
                const int c0 = wn * NT * 8 + ni * 8 + g;
                b[ni][0] = *(const uint32_t*)&Ws[c0 * LDSR + kk + 2 * t];
                b[ni][1] = *(const uint32_t*)&Ws[c0 * LDSR + kk + 8 + 2 * t];
            }
            #pragma unroll
            for (int mi = 0; mi < 4; mi++)
                #pragma unroll
                for (int ni = 0; ni < NT; ni++)
                    mma_f16(acc[mi][ni], a[mi], b[ni]);
        }
        __syncthreads();
    }

    // ---- epilogue ----
    #pragma unroll
    for (int mi = 0; mi < 4; mi++) {
        const int row = m0 + wm * 64 + mi * 16 + g;
        #pragma unroll
        for (int ni = 0; ni < NT; ni++) {
            const int col = n0 + wn * NT * 8 + ni * 8 + 2 * t;
            float2 bv = *(const float2*)&bias[col];
            float o0 = acc[mi][ni][0] + bv.x;
            float o1 = acc[mi][ni][1] + bv.y;
            float o2 = acc[mi][ni][2] + bv.x;
            float o3 = acc[mi][ni][3] + bv.y;
            if (EPI == 1) {
                o0 = gelu_exact(o0); o1 = gelu_exact(o1);
                o2 = gelu_exact(o2); o3 = gelu_exact(o3);
            } else if (EPI == 2) {
                float2 r0 = *(const float2*)&R[(size_t)row * Nn + col];
                float2 r1 = *(const float2*)&R[(size_t)(row + 8) * Nn + col];
                o0 += r0.x; o1 += r0.y; o2 += r1.x; o3 += r1.y;
            }
            if (OUTH) {
                __half* C = (__half*)Cv;
                *(__half2*)&C[(size_t)row * Nn + col] = __floats2half2_rn(o0, o1);
                *(__half2*)&C[(size_t)(row + 8) * Nn + col] = __floats2half2_rn(o2, o3);
            } else {
                float* C = (float*)Cv;
                *(float2*)&C[(size_t)row * Nn + col] = make_float2(o0, o1);
                *(float2*)&C[(size_t)(row + 8) * Nn + col] = make_float2(o2, o3);
            }
        }
    }
}

// ================= split-tf32 GEMM (fp32-grade) for f projection =================
// BN=64 fixed. C fp32.
__global__ void __launch_bounds__(256) fsplit_gemm(
    const float* __restrict__ A, const float* __restrict__ W,
    const float* __restrict__ bias, float* __restrict__ C, int M, int Nn, int K)
{
    extern __shared__ float sm[];
    constexpr int BN = 64;
    constexpr int LDSR = 36;
    constexpr int ABUF = 128 * LDSR;
    constexpr int BBUF = BN * LDSR;
    constexpr int NT = BN / 32;
    constexpr int A4 = 128 * 8;
    constexpr int TOT4 = A4 + BN * 8;

    const int tid  = threadIdx.x;
    const int lane = tid & 31, warp = tid >> 5;
    const int wm = warp & 1, wn = warp >> 1;
    const int g = lane >> 2, t = lane & 3;
    const int m0 = blockIdx.y * 128;
    const int n0 = blockIdx.x * BN;
    const int NC = K / 32;

    float acc[4][NT][4];
    #pragma unroll
    for (int mi = 0; mi < 4; mi++)
        #pragma unroll
        for (int ni = 0; ni < NT; ni++)
            #pragma unroll
            for (int r = 0; r < 4; r++) acc[mi][ni][r] = 0.f;

    float* Ahi = sm;
    float* Alo = sm + ABUF;
    float* Whi = sm + 2 * ABUF;
    float* Wlo = Whi + BBUF;
    for (int c = 0; c < NC; c++) {
        const int k0 = c * 32;
        __syncthreads();
        #pragma unroll
        for (int v = tid; v < TOT4; v += 256) {
            const float* src; float *dh, *dl;
            if (v < A4) {
                int row = v >> 3, q = v & 7;
                src = A + (size_t)(m0 + row) * K + k0 + q * 4;
                dh = Ahi + row * LDSR + q * 4; dl = Alo + row * LDSR + q * 4;
            } else {
                int u = v - A4; int row = u >> 3, q = u & 7;
                src = W + (size_t)(n0 + row) * K + k0 + q * 4;
                dh = Whi + row * LDSR + q * 4; dl = Wlo + row * LDSR + q * 4;
            }
            float4 tv = *(const float4*)src;
            float4 hi, lo;
            hi.x = tf32_round(tv.x); lo.x = tf32_round(tv.x - hi.x);
            hi.y = tf32_round(tv.y); lo.y = tf32_round(tv.y - hi.y);
            hi.z = tf32_round(tv.z); lo.z = tf32_round(tv.z - hi.z);
            hi.w = tf32_round(tv.w); lo.w = tf32_round(tv.w - hi.w);
            *(float4*)dh = hi; *(float4*)dl = lo;
        }
        __syncthreads();
        #pragma unroll
        for (int kk = 0; kk < 32; kk += 8) {
            uint32_t ah[4][4], al[4][4], bh[NT][2], bl[NT][2];
            #pragma unroll
            for (int mi = 0; mi < 4; mi++) {
                const int r0 = wm * 64 + mi * 16 + g;
                ah[mi][0] = __float_as_uint(Ahi[r0 * LDSR + kk + t]);
                ah[mi][1] = __float_as_uint(Ahi[(r0 + 8) * LDSR + kk + t]);
                ah[mi][2] = __float_as_uint(Ahi[r0 * LDSR + kk + t + 4]);
                ah[mi][3] = __float_as_uint(Ahi[(r0 + 8) * LDSR + kk + t + 4]);
                al[mi][0] = __float_as_uint(Alo[r0 * LDSR + kk + t]);
                al[mi][1] = __float_as_uint(Alo[(r0 + 8) * LDSR + kk + t]);
                al[mi][2] = __float_as_uint(Alo[r0 * LDSR + kk + t + 4]);
                al[mi][3] = __float_as_uint(Alo[(r0 + 8) * LDSR + kk + t + 4]);
            }
            #pragma unroll
            for (int ni = 0; ni < NT; ni++) {
                const int c0 = wn * NT * 8 + ni * 8 + g;
                bh[ni][0] = __float_as_uint(Whi[c0 * LDSR + kk + t]);
                bh[ni][1] = __float_as_uint(Whi[c0 * LDSR + kk + t + 4]);
                bl[ni][0] = __float_as_uint(Wlo[c0 * LDSR + kk + t]);
                bl[ni][1] = __float_as_uint(Wlo[c0 * LDSR + kk + t + 4]);
            }
            #pragma unroll
            for (int mi = 0; mi < 4; mi++)
                #pragma unroll
                for (int ni = 0; ni < NT; ni++) {
                    mma_tf32(acc[mi][ni], ah[mi], bh[ni]);
                    mma_tf32(acc[mi][ni], ah[mi], bl[ni]);
                    mma_tf32(acc[mi][ni], al[mi], bh[ni]);
                }
        }
    }
    #pragma unroll
    for (int mi = 0; mi < 4; mi++) {
        const int row = m0 + wm * 64 + mi * 16 + g;
        #pragma unroll
        for (int ni = 0; ni < NT; ni++) {
            const int col = n0 + wn * NT * 8 + ni * 8 + 2 * t;
            float2 bv = *(const float2*)&bias[col];
            *(float2*)&C[(size_t)row * Nn + col] =
                make_float2(acc[mi][ni][0] + bv.x, acc[mi][ni][1] + bv.y);
            *(float2*)&C[(size_t)(row + 8) * Nn + col] =
                make_float2(acc[mi][ni][2] + bv.x, acc[mi][ni][3] + bv.y);
        }
    }
}

// ---------------- fp32 -> fp16 conversion ----------------
__global__ void __launch_bounds__(256) cvt_kernel(const float* __restrict__ src,
                                                  __half* __restrict__ dst, int n4)
{
    int i = blockIdx.x * 256 + threadIdx.x;
    if (i >= n4) return;
    float4 v = *(const float4*)&src[i * 4];
    __half2* d = (__half2*)&dst[i * 4];
    d[0] = __floats2half2_rn(v.x, v.y);
    d[1] = __floats2half2_rn(v.z, v.w);
}

// ---------------- LayerNorm: optional fp32 + fp16 outputs ----------------
__global__ void __launch_bounds__(256) ln_kernel(const float* __restrict__ x,
    const float* __restrict__ w, const float* __restrict__ b,
    float* __restrict__ outf, __half* __restrict__ outh)
{
    int t = blockIdx.x;
    const float* xr = x + (size_t)t * DD;
    int tid = threadIdx.x;
    float v0 = xr[tid], v1 = xr[tid + 256], v2 = xr[tid + 512];
    float s  = v0 + v1 + v2;
    float ss = v0*v0 + v1*v1 + v2*v2;
    #pragma unroll
    for (int o = 16; o; o >>= 1) {
        s  += __shfl_xor_sync(0xffffffffu, s,  o);
        ss += __shfl_xor_sync(0xffffffffu, ss, o);
    }
    __shared__ float rs[8], rss[8];
    if ((tid & 31) == 0) { rs[tid >> 5] = s; rss[tid >> 5] = ss; }
    __syncthreads();
    float S = 0.f, SS = 0.f;
    #pragma unroll
    for (int i = 0; i < 8; i++) { S += rs[i]; SS += rss[i]; }
    float mean = S * (1.f / DD);
    float var  = SS * (1.f / DD) - mean * mean;
    float rstd = rsqrtf(var + 1e-5f);
    float o0 = (v0 - mean) * rstd * w[tid]       + b[tid];
    float o1 = (v1 - mean) * rstd * w[tid + 256] + b[tid + 256];
    float o2 = (v2 - mean) * rstd * w[tid + 512] + b[tid + 512];
    if (outf) {
        float* orow = outf + (size_t)t * DD;
        orow[tid] = o0; orow[tid + 256] = o1; orow[tid + 512] = o2;
    }
    if (outh) {
        __half* hrow = outh + (size_t)t * DD;
        hrow[tid] = __float2half_rn(o0);
        hrow[tid + 256] = __float2half_rn(o1);
        hrow[tid + 512] = __float2half_rn(o2);
    }
}

// ---------------- Pooling ----------------
__global__ void __launch_bounds__(384) pool_kernel()
{
    int be  = blockIdx.x;
    int bb  = be >> 3, e = be & 7;
    int tid = threadIdx.x;
    int m = tid / HDIM, c = tid % HDIM;
    int pw = m >> 2, ph = m & 3;
    float sf = 0.f, sv = 0.f;
    #pragma unroll 4
    for (int ws = 0; ws < 8; ws++) {
        #pragma unroll
        for (int hs = 0; hs < 8; hs++) {
            int n = (pw * 8 + ws) * PS + ph * 8 + hs;
            size_t idx = (size_t)(bb * NTOK + n) * INNER + e * HDIM + c;
            sf += g_f[idx];
            sv += g_v[idx];
        }
    }
    sf *= (1.f / 64.f); sv *= (1.f / 64.f);
    __shared__ float cen_s[MCEN][HDIM];
    cen_s[m][c] = sf;
    __syncthreads();
    float ssq = 0.f;
    #pragma unroll
    for (int cc = 0; cc < HDIM; cc++) { float t = cen_s[m][cc]; ssq += t * t; }
    float denom = fmaxf(sqrtf(ssq), 1e-12f);
    size_t oidx = ((size_t)be * MCEN + m) * HDIM + c;
    g_cn[oidx]   = sf / denom;
    g_vcen[oidx] = sv;
}

// ---------------- Assignment ----------------
__global__ void __launch_bounds__(256) assign_kernel(const float* __restrict__ alpha_p,
                                                     const float* __restrict__ beta_p)
{
    int be = blockIdx.x;
    int bb = be >> 3, e = be & 7;
    __shared__ float cns[MCEN][HDIM];
    for (int t = threadIdx.x; t < MCEN * HDIM; t += blockDim.x)
        cns[t / HDIM][t % HDIM] = g_cn[(size_t)be * MCEN * HDIM + t];
    __syncthreads();
    float alpha = *alpha_p, beta = *beta_p;
    for (int n = threadIdx.x; n < NTOK; n += blockDim.x) {
        const float* xv = g_f + (size_t)(bb * NTOK + n) * INNER + e * HDIM;
        float x[HDIM]; float ss = 0.f;
        #pragma unroll
        for (int c = 0; c < HDIM; c++) { x[c] = xv[c]; ss += x[c] * x[c]; }
        float inv = 1.f / fmaxf(sqrtf(ss), 1e-12f);
        float best = -1e30f; int bm = 0;
        #pragma unroll
        for (int m = 0; m < MCEN; m++) {
            float d = 0.f;
            #pragma unroll
            for (int c = 0; c < HDIM; c++) d = fmaf(cns[m][c], x[c], d);
            d *= inv;
            float dist = sqrtf(fmaxf(2.f - 2.f * d, 1e-12f));
            float sp = beta + alpha * expf(-dist);
            float sim = sp > 0.f ? sp : 0.2f * sp;
            if (sim > best) { best = sim; bm = m; }
        }
        g_assign[(size_t)be * NTOK + n] = bm;
        g_simval[(size_t)be * NTOK + n] = best;
    }
}

// ---------------- Weighted reduce to centers ----------------
__global__ void __launch_bounds__(192) outc_kernel()
{
    int m  = blockIdx.x;
    int be = blockIdx.y;
    int bb = be >> 3, e = be & 7;
    int tid = threadIdx.x;
    int c = tid % HDIM, g = tid / HDIM;
    float acc = 0.f; int cnt = 0;
    for (int n = g * 128; n < g * 128 + 128; n++) {
        int a = g_assign[(size_t)be * NTOK + n];
        if (a == m) {
            float s = g_simval[(size_t)be * NTOK + n];
            acc = fmaf(s, g_v[(size_t)(bb * NTOK + n) * INNER + e * HDIM + c], acc);
            cnt++;
        }
    }
    __shared__ float pa[8][HDIM];
    __shared__ int   pc[8];
    pa[g][c] = acc;
    if (c == 0) pc[g] = cnt;
    __syncthreads();
    if (g == 0) {
        float tot = 0.f; int ct = 0;
        #pragma unroll
        for (int gg = 0; gg < 8; gg++) { tot += pa[gg][c]; ct += pc[gg]; }
        size_t oidx = ((size_t)be * MCEN + m) * HDIM + c;
        g_outc[oidx] = (tot + g_vcen[oidx]) / ((float)ct + 1.f);
    }
}

// ---------------- Scatter (fp16 output for proj GEMM) ----------------
__global__ void __launch_bounds__(256) oi_kernel()
{
    size_t idx = (size_t)blockIdx.x * blockDim.x + threadIdx.x;
    if (idx >= (size_t)T_TOT * INNER) return;
    int t = (int)(idx / INNER), i = (int)(idx % INNER);
    int bb = t >> 10, n = t & (NTOK - 1);
    int e = i / HDIM, c = i % HDIM;
    int be = bb * HEADS + e;
    int m = g_assign[(size_t)be * NTOK + n];
    float val = g_simval[(size_t)be * NTOK + n] * g_outc[((size_t)be * MCEN + m) * HDIM + c];
    g_oih[idx] = __float2half_rn(val);
}

// ---------------- Launch ----------------
extern "C" void kernel_launch(void* const* d_in, const int* in_sizes, int n_in,
                              void* d_out, int out_size)
{
    const float* x      = (const float*)d_in[0];
    const float* ln1_w  = (const float*)d_in[1];
    const float* ln1_b  = (const float*)d_in[2];
    const float* f_w    = (const float*)d_in[3];
    const float* f_b    = (const float*)d_in[4];
    const float* v_w    = (const float*)d_in[5];
    const float* v_b    = (const float*)d_in[6];
    const float* proj_w = (const float*)d_in[7];
    const float* proj_b = (const float*)d_in[8];
    const float* alpha  = (const float*)d_in[9];
    const float* beta   = (const float*)d_in[10];
    const float* ln2_w  = (const float*)d_in[11];
    const float* ln2_b  = (const float*)d_in[12];
    const float* fc1_w  = (const float*)d_in[13];
    const float* fc1_b  = (const float*)d_in[14];
    const float* fc2_w  = (const float*)d_in[15];
    const float* fc2_b  = (const float*)d_in[16];
    float* out = (float*)d_out;

    float *p_x1, *p_f, *p_v, *p_h;
    __half *p_x1h, *p_oih, *p_y1h, *p_acth, *p_vwh, *p_pwh, *p_f1wh, *p_f2wh;
    cudaGetSymbolAddress((void**)&p_x1,   g_x1);
    cudaGetSymbolAddress((void**)&p_x1h,  g_x1h);
    cudaGetSymbolAddress((void**)&p_f,    g_f);
    cudaGetSymbolAddress((void**)&p_v,    g_v);
    cudaGetSymbolAddress((void**)&p_oih,  g_oih);
    cudaGetSymbolAddress((void**)&p_h,    g_h);
    cudaGetSymbolAddress((void**)&p_y1h,  g_y1h);
    cudaGetSymbolAddress((void**)&p_acth, g_acth);
    cudaGetSymbolAddress((void**)&p_vwh,  g_vwh);
    cudaGetSymbolAddress((void**)&p_pwh,  g_pwh);
    cudaGetSymbolAddress((void**)&p_f1wh, g_f1wh);
    cudaGetSymbolAddress((void**)&p_f2wh, g_f2wh);

    const int SM_SPLIT = (2 * 128 * 36 + 2 * 64 * 36) * 4;       // 55296
    const int SM_H128  = 2 * (128 * 40 + 128 * 40) * 2;          // 40960
    const int SM_H64   = 2 * (128 * 40 +  64 * 40) * 2;          // 30720
    cudaFuncSetAttribute(fsplit_gemm, cudaFuncAttributeMaxDynamicSharedMemorySize, SM_SPLIT);
    cudaFuncSetAttribute(hgemm<64, 0, false>,  cudaFuncAttributeMaxDynamicSharedMemorySize, SM_H64);
    cudaFuncSetAttribute(hgemm<128, 1, true >, cudaFuncAttributeMaxDynamicSharedMemorySize, SM_H128);
    cudaFuncSetAttribute(hgemm<128, 2, false>, cudaFuncAttributeMaxDynamicSharedMemorySize, SM_H128);

    // 0) convert weights to fp16
    cvt_kernel<<<(INNER * DD / 4 + 255) / 256, 256>>>(v_w,    p_vwh,  INNER * DD / 4);
    cvt_kernel<<<(DD * INNER / 4 + 255) / 256, 256>>>(proj_w, p_pwh,  DD * INNER / 4);
    cvt_kernel<<<(HID * DD / 4 + 255) / 256, 256>>>(fc1_w,   p_f1wh, HID * DD / 4);
    cvt_kernel<<<(DD * HID / 4 + 255) / 256, 256>>>(fc2_w,   p_f2wh, DD * HID / 4);

    // 1) LN1 -> fp32 (f) + fp16 (v)
    ln_kernel<<<T_TOT, 256>>>(x, ln1_w, ln1_b, p_x1, p_x1h);

    // 2) f projection (split-tf32, fp32-grade: feeds argmax)
    fsplit_gemm<<<dim3(INNER / 64, T_TOT / 128), 256, SM_SPLIT>>>(
        p_x1, f_w, f_b, p_f, T_TOT, INNER, DD);
    // 3) v projection (fp16)
    hgemm<64, 0, false><<<dim3(INNER / 64, T_TOT / 128), 256, SM_H64>>>(
        p_x1h, p_vwh, v_b, nullptr, p_v, T_TOT, INNER, DD);

    // 4-7) cluster path
    pool_kernel<<<BE, 384>>>();
    assign_kernel<<<BE, 256>>>(alpha, beta);
    outc_kernel<<<dim3(MCEN, BE), 192>>>();
    oi_kernel<<<(T_TOT * INNER + 255) / 256, 256>>>();

    // 8) proj + residual x -> h (fp16 GEMM, fp32 out)
    hgemm<128, 2, false><<<dim3(DD / 128, T_TOT / 128), 256, SM_H128>>>(
        p_oih, p_pwh, proj_b, x, p_h, T_TOT, DD, INNER);

    // 9) LN2 -> fp16 only
    ln_kernel<<<T_TOT, 256>>>(p_h, ln2_w, ln2_b, nullptr, p_y1h);

    // 10) fc1 + GELU -> fp16 activations
    hgemm<128, 1, true><<<dim3(HID / 128, T_TOT / 128), 256, SM_H128>>>(
        p_y1h, p_f1wh, fc1_b, nullptr, p_acth, T_TOT, HID, DD);

    // 11) fc2 + residual h -> out (fp32)
    hgemm<128, 2, false><<<dim3(DD / 128, T_TOT / 128), 256, SM_H128>>>(
        p_acth, p_f2wh, fc2_b, p_h, out, T_TOT, DD, HID);
}

// round 16
// speedup vs baseline: 4.8861x; 1.0481x over previous
#include <cuda_runtime.h>
#include <cuda_fp16.h>
#include <math.h>
#include <stdint.h>

// ---------------- Problem constants ----------------
#define BB    16
#define PS    32
#define NTOK  1024
#define DD    768
#define HEADS 8
#define HDIM  24
#define MCEN  16
#define INNER 192
#define HID   3072
#define T_TOT (BB*NTOK)   // 16384
#define BE    (BB*HEADS)  // 128

#define SPLIT_SCALE   2048.0f
#define SPLIT_ISCALE  (1.0f/2048.0f)

// ---------------- Scratch (device globals) ----------------
__device__ __half g_x1h [T_TOT*DD];     // LN1(x) fp16 hi (v GEMM + f split hi)
__device__ __half g_x1l [T_TOT*DD];     // LN1(x) fp16 lo' (scaled residual)
__device__ float  g_f  [T_TOT*INNER];
__device__ float  g_v  [T_TOT*INNER];
__device__ float  g_cn [BE*MCEN*HDIM];
__device__ float  g_vcen[BE*MCEN*HDIM];
__device__ int    g_assign[BE*NTOK];
__device__ float  g_simval[BE*NTOK];
__device__ float  g_outc[BE*MCEN*HDIM];
__device__ __half g_oih[T_TOT*INNER];
__device__ float  g_h  [T_TOT*DD];
__device__ __half g_y1h[T_TOT*DD];
__device__ __half g_acth[T_TOT*HID];
// fp16 weights (converted per launch)
__device__ __half g_fwh [INNER*DD];     // f weight hi
__device__ __half g_fwl [INNER*DD];     // f weight lo' (scaled)
__device__ __half g_vwh [INNER*DD];
__device__ __half g_pwh [DD*INNER];
__device__ __half g_f1wh[HID*DD];
__device__ __half g_f2wh[DD*HID];

// ================= helpers =================
__device__ __forceinline__ float gelu_exact(float x) {
    return 0.5f * x * (1.f + erff(x * 0.70710678118654752440f));
}
__device__ __forceinline__ void mma_f16(float* d, const uint32_t* a, const uint32_t* b) {
    asm volatile(
        "mma.sync.aligned.m16n8k16.row.col.f32.f16.f16.f32 "
        "{%0,%1,%2,%3}, {%4,%5,%6,%7}, {%8,%9}, {%0,%1,%2,%3};"
        : "+f"(d[0]), "+f"(d[1]), "+f"(d[2]), "+f"(d[3])
        : "r"(a[0]), "r"(a[1]), "r"(a[2]), "r"(a[3]), "r"(b[0]), "r"(b[1]));
}

#define CP_ASYNC16(dst32, src) \
    asm volatile("cp.async.cg.shared.global [%0], [%1], 16;" :: "r"(dst32), "l"(src))
#define CP_COMMIT() asm volatile("cp.async.commit_group;" ::: "memory")
#define CP_WAIT1()  asm volatile("cp.async.wait_group 1;" ::: "memory")
#define CP_WAIT0()  asm volatile("cp.async.wait_group 0;" ::: "memory")

// ================= fp16 tensor-core GEMM =================
// C[M][Nn] = epi(A[M][K] * W[Nn][K]^T + bias). BM=128, BK=32, 256 thr.
// Warp grid 2(m) x 4(n). EPI: 0=store, 1=GELU, 2=+residual. OUTH: fp16 store.
template<int BN, int EPI, bool OUTH>
__global__ void __launch_bounds__(256) hgemm(
    const __half* __restrict__ A, const __half* __restrict__ W,
    const float* __restrict__ bias, const float* __restrict__ R,
    void* __restrict__ Cv, int M, int Nn, int K)
{
    extern __shared__ __half smh[];
    constexpr int LDSR = 40;
    constexpr int ABUF = 128 * LDSR;
    constexpr int BBUF = BN * LDSR;
    constexpr int NT   = BN / 32;
    constexpr int AU   = 128 * 4;
    constexpr int TOTU = AU + BN * 4;

    const int tid  = threadIdx.x;
    const int lane = tid & 31, warp = tid >> 5;
    const int wm = warp & 1, wn = warp >> 1;
    const int g = lane >> 2, t = lane & 3;
    const int m0 = blockIdx.y * 128;
    const int n0 = blockIdx.x * BN;
    const int NC = K / 32;

    float acc[4][NT][4];
    #pragma unroll
    for (int mi = 0; mi < 4; mi++)
        #pragma unroll
        for (int ni = 0; ni < NT; ni++)
            #pragma unroll
            for (int r = 0; r < 4; r++) acc[mi][ni][r] = 0.f;

    auto load_chunk = [&](int c, int p) {
        __half* dst = smh + p * (ABUF + BBUF);
        const int k0 = c * 32;
        #pragma unroll
        for (int v = tid; v < TOTU; v += 256) {
            const __half* src; __half* d;
            int row = v >> 2, q = v & 3;
            if (row < 128) {
                src = A + (size_t)(m0 + row) * K + k0 + q * 8;
                d   = dst + row * LDSR + q * 8;
            } else {
                int r2 = row - 128;
                src = W + (size_t)(n0 + r2) * K + k0 + q * 8;
                d   = dst + ABUF + r2 * LDSR + q * 8;
            }
            CP_ASYNC16((uint32_t)__cvta_generic_to_shared(d), src);
        }
        CP_COMMIT();
    };

    load_chunk(0, 0);
    for (int c = 0; c < NC; c++) {
        const int p = c & 1;
        if (c + 1 < NC) { load_chunk(c + 1, p ^ 1); CP_WAIT1(); }
        else            { CP_WAIT0(); }
        __syncthreads();

        const __half* As = smh + p * (ABUF + BBUF);
        const __half* Ws = As + ABUF;
        #pragma unroll
        for (int kk = 0; kk < 32; kk += 16) {
            uint32_t a[4][4], b[NT][2];
            #pragma unroll
            for (int mi = 0; mi < 4; mi++) {
                const int r0 = wm * 64 + mi * 16 + g;
                a[mi][0] = *(const uint32_t*)&As[r0 * LDSR + kk + 2 * t];
                a[mi][1] = *(const uint32_t*)&As[(r0 + 8) * LDSR + kk + 2 * t];
                a[mi][2] = *(const uint32_t*)&As[r0 * LDSR + kk + 8 + 2 * t];
                a[mi][3] = *(const uint32_t*)&As[(r0 + 8) * LDSR + kk + 8 + 2 * t];
            }
            #pragma unroll
            for (int ni = 0; ni < NT; ni++) {
                const int c0 = wn * NT * 8 + ni * 8 + g;
                b[ni][0] = *(const uint32_t*)&Ws[c0 * LDSR + kk + 2 * t];
                b[ni][1] = *(const uint32_t*)&Ws[c0 * LDSR + kk + 8 + 2 * t];
            }
            #pragma unroll
            for (int mi = 0; mi < 4; mi++)
                #pragma unroll
                for (int ni = 0; ni < NT; ni++)
                    mma_f16(acc[mi][ni], a[mi], b[ni]);
        }
        __syncthreads();
    }

    #pragma unroll
    for (int mi = 0; mi < 4; mi++) {
        const int row = m0 + wm * 64 + mi * 16 + g;
        #pragma unroll
        for (int ni = 0; ni < NT; ni++) {
            const int col = n0 + wn * NT * 8 + ni * 8 + 2 * t;
            float2 bv = *(const float2*)&bias[col];
            float o0 = acc[mi][ni][0] + bv.x;
            float o1 = acc[mi][ni][1] + bv.y;
            float o2 = acc[mi][ni][2] + bv.x;
            float o3 = acc[mi][ni][3] + bv.y;
            if (EPI == 1) {
                o0 = gelu_exact(o0); o1 = gelu_exact(o1);
                o2 = gelu_exact(o2); o3 = gelu_exact(o3);
            } else if (EPI == 2) {
                float2 r0 = *(const float2*)&R[(size_t)row * Nn + col];
                float2 r1 = *(const float2*)&R[(size_t)(row + 8) * Nn + col];
                o0 += r0.x; o1 += r0.y; o2 += r1.x; o3 += r1.y;
            }
            if (OUTH) {
                __half* C = (__half*)Cv;
                *(__half2*)&C[(size_t)row * Nn + col] = __floats2half2_rn(o0, o1);
                *(__half2*)&C[(size_t)(row + 8) * Nn + col] = __floats2half2_rn(o2, o3);
            } else {
                float* C = (float*)Cv;
                *(float2*)&C[(size_t)row * Nn + col] = make_float2(o0, o1);
                *(float2*)&C[(size_t)(row + 8) * Nn + col] = make_float2(o2, o3);
            }
        }
    }
}

// ================= scaled-fp16-split GEMM (fp32-grade) for f projection =================
// C = (Ah+Al/S)(Wh+Wl/S)^T + bias ≈ Ah·Wh + (Ah·Wl + Al·Wh)/S.  BN=64, pipelined.
__global__ void __launch_bounds__(256) fsplit16_gemm(
    const __half* __restrict__ Ah, const __half* __restrict__ Al,
    const __half* __restrict__ Wh, const __half* __restrict__ Wl,
    const float* __restrict__ bias, float* __restrict__ C, int M, int Nn, int K)
{
    extern __shared__ __half smh[];
    constexpr int BN = 64;
    constexpr int LDSR = 40;
    constexpr int ABUF = 128 * LDSR;     // per operand-half
    constexpr int BBUF = BN * LDSR;
    constexpr int STG  = 2 * ABUF + 2 * BBUF;
    constexpr int NT   = BN / 32;        // 2
    constexpr int AU   = 128 * 4;        // 16B units per A operand
    constexpr int WU   = BN * 4;
    constexpr int TOTU = 2 * AU + 2 * WU;

    const int tid  = threadIdx.x;
    const int lane = tid & 31, warp = tid >> 5;
    const int wm = warp & 1, wn = warp >> 1;
    const int g = lane >> 2, t = lane & 3;
    const int m0 = blockIdx.y * 128;
    const int n0 = blockIdx.x * BN;
    const int NC = K / 32;

    float ach[4][NT][4], acl[4][NT][4];
    #pragma unroll
    for (int mi = 0; mi < 4; mi++)
        #pragma unroll
        for (int ni = 0; ni < NT; ni++)
            #pragma unroll
            for (int r = 0; r < 4; r++) { ach[mi][ni][r] = 0.f; acl[mi][ni][r] = 0.f; }

    auto load_chunk = [&](int c, int p) {
        __half* dst = smh + p * STG;
        const int k0 = c * 32;
        #pragma unroll
        for (int v = tid; v < TOTU; v += 256) {
            const __half* src; __half* d;
            if (v < AU) {                 // A hi
                int row = v >> 2, q = v & 3;
                src = Ah + (size_t)(m0 + row) * K + k0 + q * 8;
                d   = dst + row * LDSR + q * 8;
            } else if (v < 2 * AU) {      // A lo
                int u = v - AU; int row = u >> 2, q = u & 3;
                src = Al + (size_t)(m0 + row) * K + k0 + q * 8;
                d   = dst + ABUF + row * LDSR + q * 8;
            } else if (v < 2 * AU + WU) { // W hi
                int u = v - 2 * AU; int row = u >> 2, q = u & 3;
                src = Wh + (size_t)(n0 + row) * K + k0 + q * 8;
                d   = dst + 2 * ABUF + row * LDSR + q * 8;
            } else {                      // W lo
                int u = v - 2 * AU - WU; int row = u >> 2, q = u & 3;
                src = Wl + (size_t)(n0 + row) * K + k0 + q * 8;
                d   = dst + 2 * ABUF + BBUF + row * LDSR + q * 8;
            }
            CP_ASYNC16((uint32_t)__cvta_generic_to_shared(d), src);
        }
        CP_COMMIT();
    };

    load_chunk(0, 0);
    for (int c = 0; c < NC; c++) {
        const int p = c & 1;
        if (c + 1 < NC) { load_chunk(c + 1, p ^ 1); CP_WAIT1(); }
        else            { CP_WAIT0(); }
        __syncthreads();

        const __half* Ash = smh + p * STG;
        const __half* Asl = Ash + ABUF;
        const __half* Wsh = Ash + 2 * ABUF;
        const __half* Wsl = Wsh + BBUF;
        #pragma unroll
        for (int kk = 0; kk < 32; kk += 16) {
            uint32_t ah[4][4], al[4][4], bh[NT][2], bl[NT][2];
            #pragma unroll
            for (int mi = 0; mi < 4; mi++) {
                const int r0 = wm * 64 + mi * 16 + g;
                ah[mi][0] = *(const uint32_t*)&Ash[r0 * LDSR + kk + 2 * t];
                ah[mi][1] = *(const uint32_t*)&Ash[(r0 + 8) * LDSR + kk + 2 * t];
                ah[mi][2] = *(const uint32_t*)&Ash[r0 * LDSR + kk + 8 + 2 * t];
                ah[mi][3] = *(const uint32_t*)&Ash[(r0 + 8) * LDSR + kk + 8 + 2 * t];
                al[mi][0] = *(const uint32_t*)&Asl[r0 * LDSR + kk + 2 * t];
                al[mi][1] = *(const uint32_t*)&Asl[(r0 + 8) * LDSR + kk + 2 * t];
                al[mi][2] = *(const uint32_t*)&Asl[r0 * LDSR + kk + 8 + 2 * t];
                al[mi][3] = *(const uint32_t*)&Asl[(r0 + 8) * LDSR + kk + 8 + 2 * t];
            }
            #pragma unroll
            for (int ni = 0; ni < NT; ni++) {
                const int c0 = wn * NT * 8 + ni * 8 + g;
                bh[ni][0] = *(const uint32_t*)&Wsh[c0 * LDSR + kk + 2 * t];
                bh[ni][1] = *(const uint32_t*)&Wsh[c0 * LDSR + kk + 8 + 2 * t];
                bl[ni][0] = *(const uint32_t*)&Wsl[c0 * LDSR + kk + 2 * t];
                bl[ni][1] = *(const uint32_t*)&Wsl[c0 * LDSR + kk + 8 + 2 * t];
            }
            #pragma unroll
            for (int mi = 0; mi < 4; mi++)
                #pragma unroll
                for (int ni = 0; ni < NT; ni++) {
                    mma_f16(ach[mi][ni], ah[mi], bh[ni]);
                    mma_f16(acl[mi][ni], ah[mi], bl[ni]);
                    mma_f16(acl[mi][ni], al[mi], bh[ni]);
                }
        }
        __syncthreads();
    }

    #pragma unroll
    for (int mi = 0; mi < 4; mi++) {
        const int row = m0 + wm * 64 + mi * 16 + g;
        #pragma unroll
        for (int ni = 0; ni < NT; ni++) {
            const int col = n0 + wn * NT * 8 + ni * 8 + 2 * t;
            float2 bv = *(const float2*)&bias[col];
            float o0 = fmaf(acl[mi][ni][0], SPLIT_ISCALE, ach[mi][ni][0]) + bv.x;
            float o1 = fmaf(acl[mi][ni][1], SPLIT_ISCALE, ach[mi][ni][1]) + bv.y;
            float o2 = fmaf(acl[mi][ni][2], SPLIT_ISCALE, ach[mi][ni][2]) + bv.x;
            float o3 = fmaf(acl[mi][ni][3], SPLIT_ISCALE, ach[mi][ni][3]) + bv.y;
            *(float2*)&C[(size_t)row * Nn + col] = make_float2(o0, o1);
            *(float2*)&C[(size_t)(row + 8) * Nn + col] = make_float2(o2, o3);
        }
    }
}

// ---------------- fp32 -> fp16 conversion (plain) ----------------
__global__ void __launch_bounds__(256) cvt_kernel(const float* __restrict__ src,
                                                  __half* __restrict__ dst, int n4)
{
    int i = blockIdx.x * 256 + threadIdx.x;
    if (i >= n4) return;
    float4 v = *(const float4*)&src[i * 4];
    __half2* d = (__half2*)&dst[i * 4];
    d[0] = __floats2half2_rn(v.x, v.y);
    d[1] = __floats2half2_rn(v.z, v.w);
}

// ---------------- fp32 -> fp16 hi/lo split conversion ----------------
__global__ void __launch_bounds__(256) cvt_split_kernel(const float* __restrict__ src,
    __half* __restrict__ dh, __half* __restrict__ dl, int n4)
{
    int i = blockIdx.x * 256 + threadIdx.x;
    if (i >= n4) return;
    float4 v = *(const float4*)&src[i * 4];
    __half h0 = __float2half_rn(v.x), h1 = __float2half_rn(v.y);
    __half h2 = __float2half_rn(v.z), h3 = __float2half_rn(v.w);
    __half2* ph = (__half2*)&dh[i * 4];
    ph[0] = __halves2half2(h0, h1);
    ph[1] = __halves2half2(h2, h3);
    __half2* pl = (__half2*)&dl[i * 4];
    pl[0] = __floats2half2_rn((v.x - __half2float(h0)) * SPLIT_SCALE,
                              (v.y - __half2float(h1)) * SPLIT_SCALE);
    pl[1] = __floats2half2_rn((v.z - __half2float(h2)) * SPLIT_SCALE,
                              (v.w - __half2float(h3)) * SPLIT_SCALE);
}

// ---------------- LayerNorm: emits fp16 hi (+ optional scaled lo) ----------------
__global__ void __launch_bounds__(256) ln_kernel(const float* __restrict__ x,
    const float* __restrict__ w, const float* __restrict__ b,
    __half* __restrict__ outh, __half* __restrict__ outl)
{
    int t = blockIdx.x;
    const float* xr = x + (size_t)t * DD;
    int tid = threadIdx.x;
    float v0 = xr[tid], v1 = xr[tid + 256], v2 = xr[tid + 512];
    float s  = v0 + v1 + v2;
    float ss = v0*v0 + v1*v1 + v2*v2;
    #pragma unroll
    for (int o = 16; o; o >>= 1) {
        s  += __shfl_xor_sync(0xffffffffu, s,  o);
        ss += __shfl_xor_sync(0xffffffffu, ss, o);
    }
    __shared__ float rs[8], rss[8];
    if ((tid & 31) == 0) { rs[tid >> 5] = s; rss[tid >> 5] = ss; }
    __syncthreads();
    float S = 0.f, SS = 0.f;
    #pragma unroll
    for (int i = 0; i < 8; i++) { S += rs[i]; SS += rss[i]; }
    float mean = S * (1.f / DD);
    float var  = SS * (1.f / DD) - mean * mean;
    float rstd = rsqrtf(var + 1e-5f);
    float o0 = (v0 - mean) * rstd * w[tid]       + b[tid];
    float o1 = (v1 - mean) * rstd * w[tid + 256] + b[tid + 256];
    float o2 = (v2 - mean) * rstd * w[tid + 512] + b[tid + 512];
    __half h0 = __float2half_rn(o0), h1 = __float2half_rn(o1), h2 = __float2half_rn(o2);
    __half* hrow = outh + (size_t)t * DD;
    hrow[tid] = h0; hrow[tid + 256] = h1; hrow[tid + 512] = h2;
    if (outl) {
        __half* lrow = outl + (size_t)t * DD;
        lrow[tid]       = __float2half_rn((o0 - __half2float(h0)) * SPLIT_SCALE);
        lrow[tid + 256] = __float2half_rn((o1 - __half2float(h1)) * SPLIT_SCALE);
        lrow[tid + 512] = __float2half_rn((o2 - __half2float(h2)) * SPLIT_SCALE);
    }
}

// ---------------- Pooling ----------------
__global__ void __launch_bounds__(384) pool_kernel()
{
    int be  = blockIdx.x;
    int bb  = be >> 3, e = be & 7;
    int tid = threadIdx.x;
    int m = tid / HDIM, c = tid % HDIM;
    int pw = m >> 2, ph = m & 3;
    float sf = 0.f, sv = 0.f;
    #pragma unroll 4
    for (int ws = 0; ws < 8; ws++) {
        #pragma unroll
        for (int hs = 0; hs < 8; hs++) {
            int n = (pw * 8 + ws) * PS + ph * 8 + hs;
            size_t idx = (size_t)(bb * NTOK + n) * INNER + e * HDIM + c;
            sf += g_f[idx];
            sv += g_v[idx];
        }
    }
    sf *= (1.f / 64.f); sv *= (1.f / 64.f);
    __shared__ float cen_s[MCEN][HDIM];
    cen_s[m][c] = sf;
    __syncthreads();
    float ssq = 0.f;
    #pragma unroll
    for (int cc = 0; cc < HDIM; cc++) { float t = cen_s[m][cc]; ssq += t * t; }
    float denom = fmaxf(sqrtf(ssq), 1e-12f);
    size_t oidx = ((size_t)be * MCEN + m) * HDIM + c;
    g_cn[oidx]   = sf / denom;
    g_vcen[oidx] = sv;
}

// ---------------- Assignment ----------------
__global__ void __launch_bounds__(256) assign_kernel(const float* __restrict__ alpha_p,
                                                     const float* __restrict__ beta_p)
{
    int be = blockIdx.x;
    int bb = be >> 3, e = be & 7;
    int nbase = blockIdx.y * 256;
    __shared__ float cns[MCEN][HDIM];
    for (int t = threadIdx.x; t < MCEN * HDIM; t += blockDim.x)
        cns[t / HDIM][t % HDIM] = g_cn[(size_t)be * MCEN * HDIM + t];
    __syncthreads();
    float alpha = *alpha_p, beta = *beta_p;
    int n = nbase + threadIdx.x;
    {
        const float* xv = g_f + (size_t)(bb * NTOK + n) * INNER + e * HDIM;
        float x[HDIM]; float ss = 0.f;
        #pragma unroll
        for (int c = 0; c < HDIM; c++) { x[c] = xv[c]; ss += x[c] * x[c]; }
        float inv = 1.f / fmaxf(sqrtf(ss), 1e-12f);
        float best = -1e30f; int bm = 0;
        #pragma unroll
        for (int m = 0; m < MCEN; m++) {
            float d = 0.f;
            #pragma unroll
            for (int c = 0; c < HDIM; c++) d = fmaf(cns[m][c], x[c], d);
            d *= inv;
            float dist = sqrtf(fmaxf(2.f - 2.f * d, 1e-12f));
            float sp = beta + alpha * expf(-dist);
            float sim = sp > 0.f ? sp : 0.2f * sp;
            if (sim > best) { best = sim; bm = m; }
        }
        g_assign[(size_t)be * NTOK + n] = bm;
        g_simval[(size_t)be * NTOK + n] = best;
    }
}

// ---------------- Weighted reduce to centers ----------------
__global__ void __launch_bounds__(192) outc_kernel()
{
    int m  = blockIdx.x;
    int be = blockIdx.y;
    int bb = be >> 3, e = be & 7;
    int tid = threadIdx.x;
    int c = tid % HDIM, g = tid / HDIM;
    float acc = 0.f; int cnt = 0;
    for (int n = g * 128; n < g * 128 + 128; n++) {
        int a = g_assign[(size_t)be * NTOK + n];
        if (a == m) {
            float s = g_simval[(size_t)be * NTOK + n];
            acc = fmaf(s, g_v[(size_t)(bb * NTOK + n) * INNER + e * HDIM + c], acc);
            cnt++;
        }
    }
    __shared__ float pa[8][HDIM];
    __shared__ int   pc[8];
    pa[g][c] = acc;
    if (c == 0) pc[g] = cnt;
    __syncthreads();
    if (g == 0) {
        float tot = 0.f; int ct = 0;
        #pragma unroll
        for (int gg = 0; gg < 8; gg++) { tot += pa[gg][c]; ct += pc[gg]; }
        size_t oidx = ((size_t)be * MCEN + m) * HDIM + c;
        g_outc[oidx] = (tot + g_vcen[oidx]) / ((float)ct + 1.f);
    }
}

// ---------------- Scatter (fp16 output for proj GEMM) ----------------
__global__ void __launch_bounds__(256) oi_kernel()
{
    size_t idx = (size_t)blockIdx.x * blockDim.x + threadIdx.x;
    if (idx >= (size_t)T_TOT * INNER) return;
    int t = (int)(idx / INNER), i = (int)(idx % INNER);
    int bb = t >> 10, n = t & (NTOK - 1);
    int e = i / HDIM, c = i % HDIM;
    int be = bb * HEADS + e;
    int m = g_assign[(size_t)be * NTOK + n];
    float val = g_simval[(size_t)be * NTOK + n] * g_outc[((size_t)be * MCEN + m) * HDIM + c];
    g_oih[idx] = __float2half_rn(val);
}

// ---------------- Launch ----------------
extern "C" void kernel_launch(void* const* d_in, const int* in_sizes, int n_in,
                              void* d_out, int out_size)
{
    const float* x      = (const float*)d_in[0];
    const float* ln1_w  = (const float*)d_in[1];
    const float* ln1_b  = (const float*)d_in[2];
    const float* f_w    = (const float*)d_in[3];
    const float* f_b    = (const float*)d_in[4];
    const float* v_w    = (const float*)d_in[5];
    const float* v_b    = (const float*)d_in[6];
    const float* proj_w = (const float*)d_in[7];
    const float* proj_b = (const float*)d_in[8];
    const float* alpha  = (const float*)d_in[9];
    const float* beta   = (const float*)d_in[10];
    const float* ln2_w  = (const float*)d_in[11];
    const float* ln2_b  = (const float*)d_in[12];
    const float* fc1_w  = (const float*)d_in[13];
    const float* fc1_b  = (const float*)d_in[14];
    const float* fc2_w  = (const float*)d_in[15];
    const float* fc2_b  = (const float*)d_in[16];
    float* out = (float*)d_out;

    float *p_f, *p_v, *p_h;
    __half *p_x1h, *p_x1l, *p_oih, *p_y1h, *p_acth;
    __half *p_fwh, *p_fwl, *p_vwh, *p_pwh, *p_f1wh, *p_f2wh;
    cudaGetSymbolAddress((void**)&p_x1h,  g_x1h);
    cudaGetSymbolAddress((void**)&p_x1l,  g_x1l);
    cudaGetSymbolAddress((void**)&p_f,    g_f);
    cudaGetSymbolAddress((void**)&p_v,    g_v);
    cudaGetSymbolAddress((void**)&p_oih,  g_oih);
    cudaGetSymbolAddress((void**)&p_h,    g_h);
    cudaGetSymbolAddress((void**)&p_y1h,  g_y1h);
    cudaGetSymbolAddress((void**)&p_acth, g_acth);
    cudaGetSymbolAddress((void**)&p_fwh,  g_fwh);
    cudaGetSymbolAddress((void**)&p_fwl,  g_fwl);
    cudaGetSymbolAddress((void**)&p_vwh,  g_vwh);
    cudaGetSymbolAddress((void**)&p_pwh,  g_pwh);
    cudaGetSymbolAddress((void**)&p_f1wh, g_f1wh);
    cudaGetSymbolAddress((void**)&p_f2wh, g_f2wh);

    const int SM_H128 = 2 * (128 * 40 + 128 * 40) * 2;              // 40960
    const int SM_H64  = 2 * (128 * 40 +  64 * 40) * 2;              // 30720
    const int SM_FS   = 2 * (2 * 128 * 40 + 2 * 64 * 40) * 2;       // 61440
    cudaFuncSetAttribute(fsplit16_gemm, cudaFuncAttributeMaxDynamicSharedMemorySize, SM_FS);
    cudaFuncSetAttribute(hgemm<64, 0, false>,  cudaFuncAttributeMaxDynamicSharedMemorySize, SM_H64);
    cudaFuncSetAttribute(hgemm<128, 1, true >, cudaFuncAttributeMaxDynamicSharedMemorySize, SM_H128);
    cudaFuncSetAttribute(hgemm<128, 2, false>, cudaFuncAttributeMaxDynamicSharedMemorySize, SM_H128);

    // 0) weight conversions
    cvt_split_kernel<<<(INNER * DD / 4 + 255) / 256, 256>>>(f_w, p_fwh, p_fwl, INNER * DD / 4);
    cvt_kernel<<<(INNER * DD / 4 + 255) / 256, 256>>>(v_w,    p_vwh,  INNER * DD / 4);
    cvt_kernel<<<(DD * INNER / 4 + 255) / 256, 256>>>(proj_w, p_pwh,  DD * INNER / 4);
    cvt_kernel<<<(HID * DD / 4 + 255) / 256, 256>>>(fc1_w,   p_f1wh, HID * DD / 4);
    cvt_kernel<<<(DD * HID / 4 + 255) / 256, 256>>>(fc2_w,   p_f2wh, DD * HID / 4);

    // 1) LN1 -> fp16 hi + scaled lo
    ln_kernel<<<T_TOT, 256>>>(x, ln1_w, ln1_b, p_x1h, p_x1l);

    // 2) f projection (scaled-fp16 split, fp32-grade: feeds argmax)
    fsplit16_gemm<<<dim3(INNER / 64, T_TOT / 128), 256, SM_FS>>>(
        p_x1h, p_x1l, p_fwh, p_fwl, f_b, p_f, T_TOT, INNER, DD);
    // 3) v projection (fp16; A = LN1 hi)
    hgemm<64, 0, false><<<dim3(INNER / 64, T_TOT / 128), 256, SM_H64>>>(
        p_x1h, p_vwh, v_b, nullptr, p_v, T_TOT, INNER, DD);

    // 4-7) cluster path
    pool_kernel<<<BE, 384>>>();
    assign_kernel<<<dim3(BE, NTOK / 256), 256>>>(alpha, beta);
    outc_kernel<<<dim3(MCEN, BE), 192>>>();
    oi_kernel<<<(T_TOT * INNER + 255) / 256, 256>>>();

    // 8) proj + residual x -> h
    hgemm<128, 2, false><<<dim3(DD / 128, T_TOT / 128), 256, SM_H128>>>(
        p_oih, p_pwh, proj_b, x, p_h, T_TOT, DD, INNER);

    // 9) LN2 -> fp16
    ln_kernel<<<T_TOT, 256>>>(p_h, ln2_w, ln2_b, p_y1h, nullptr);

    // 10) fc1 + GELU -> fp16 activations
    hgemm<128, 1, true><<<dim3(HID / 128, T_TOT / 128), 256, SM_H128>>>(
        p_y1h, p_f1wh, fc1_b, nullptr, p_acth, T_TOT, HID, DD);

    // 11) fc2 + residual h -> out
    hgemm<128, 2, false><<<dim3(DD / 128, T_TOT / 128), 256, SM_H128>>>(
        p_acth, p_f2wh, fc2_b, p_h, out, T_TOT, DD, HID);
}

// round 17
// speedup vs baseline: 6.0612x; 1.2405x over previous
#include <cuda_runtime.h>
#include <cuda_fp16.h>
#include <math.h>
#include <stdint.h>

// ---------------- Problem constants ----------------
#define BB    16
#define PS    32
#define NTOK  1024
#define DD    768
#define HEADS 8
#define HDIM  24
#define MCEN  16
#define INNER 192
#define HID   3072
#define T_TOT (BB*NTOK)   // 16384
#define BE    (BB*HEADS)  // 128

#define SPLIT_SCALE   2048.0f
#define SPLIT_ISCALE  (1.0f/2048.0f)

// ---------------- Scratch (device globals) ----------------
__device__ __half g_x1h [T_TOT*DD];
__device__ __half g_x1l [T_TOT*DD];
__device__ float  g_f  [T_TOT*INNER];
__device__ float  g_v  [T_TOT*INNER];
__device__ float  g_cn [BE*MCEN*HDIM];
__device__ float  g_vcen[BE*MCEN*HDIM];
__device__ int    g_assign[BE*NTOK];
__device__ float  g_simval[BE*NTOK];
__device__ float  g_outc[BE*MCEN*HDIM];
__device__ __half g_oih[T_TOT*INNER];
__device__ float  g_h  [T_TOT*DD];
__device__ __half g_y1h[T_TOT*DD];
__device__ __half g_acth[T_TOT*HID];
__device__ __half g_fwh [INNER*DD];
__device__ __half g_fwl [INNER*DD];
__device__ __half g_vwh [INNER*DD];
__device__ __half g_pwh [DD*INNER];
__device__ __half g_f1wh[HID*DD];
__device__ __half g_f2wh[DD*HID];

// ================= helpers =================
__device__ __forceinline__ float gelu_exact(float x) {
    return 0.5f * x * (1.f + erff(x * 0.70710678118654752440f));
}
__device__ __forceinline__ void mma_f16(float* d, const uint32_t* a, const uint32_t* b) {
    asm volatile(
        "mma.sync.aligned.m16n8k16.row.col.f32.f16.f16.f32 "
        "{%0,%1,%2,%3}, {%4,%5,%6,%7}, {%8,%9}, {%0,%1,%2,%3};"
        : "+f"(d[0]), "+f"(d[1]), "+f"(d[2]), "+f"(d[3])
        : "r"(a[0]), "r"(a[1]), "r"(a[2]), "r"(a[3]), "r"(b[0]), "r"(b[1]));
}
__device__ __forceinline__ void ldsm_x4(uint32_t* r, uint32_t saddr) {
    asm volatile("ldmatrix.sync.aligned.m8n8.x4.shared.b16 {%0,%1,%2,%3}, [%4];"
        : "=r"(r[0]), "=r"(r[1]), "=r"(r[2]), "=r"(r[3]) : "r"(saddr));
}

#define CP_ASYNC16(dst32, src) \
    asm volatile("cp.async.cg.shared.global [%0], [%1], 16;" :: "r"(dst32), "l"(src))
#define CP_COMMIT() asm volatile("cp.async.commit_group;" ::: "memory")
#define CP_WAIT1()  asm volatile("cp.async.wait_group 1;" ::: "memory")
#define CP_WAIT0()  asm volatile("cp.async.wait_group 0;" ::: "memory")

// ================= fp16 tensor-core GEMM (BK=64, ldmatrix) =================
// C[M][Nn] = epi(A[M][K] * W[Nn][K]^T + bias). BM=128, 256 thr.
// Warp grid 2(m) x 4(n). EPI: 0=store, 1=GELU, 2=+residual. OUTH: fp16 store.
template<int BN, int EPI, bool OUTH>
__global__ void __launch_bounds__(256) hgemm(
    const __half* __restrict__ A, const __half* __restrict__ W,
    const float* __restrict__ bias, const float* __restrict__ R,
    void* __restrict__ Cv, int M, int Nn, int K)
{
    extern __shared__ __half smh[];
    constexpr int LDSR = 72;             // 64 data + 8 pad halves (144B stride)
    constexpr int ABUF = 128 * LDSR;
    constexpr int BBUF = BN * LDSR;
    constexpr int STG  = ABUF + BBUF;
    constexpr int NT   = BN / 32;
    constexpr int TOTU = 128 * 8 + BN * 8;   // 16B units per chunk

    const int tid  = threadIdx.x;
    const int lane = tid & 31, warp = tid >> 5;
    const int wm = warp & 1, wn = warp >> 1;
    const int g = lane >> 2, t = lane & 3;
    const int m0 = blockIdx.y * 128;
    const int n0 = blockIdx.x * BN;
    const int NC = K / 64;

    const uint32_t sbase = (uint32_t)__cvta_generic_to_shared(smh);
    // ldmatrix per-lane geometry
    const int a_row = (lane & 15);           // + r0
    const int a_k   = (lane >> 4) << 3;      // 0 or 8
    const int b_col = ((lane >> 4) << 3) + (lane & 7);  // + c0
    const int b_k   = ((lane >> 3) & 1) << 3;

    float acc[4][NT][4];
    #pragma unroll
    for (int mi = 0; mi < 4; mi++)
        #pragma unroll
        for (int ni = 0; ni < NT; ni++)
            #pragma unroll
            for (int r = 0; r < 4; r++) acc[mi][ni][r] = 0.f;

    auto load_chunk = [&](int c, int p) {
        __half* dst = smh + p * STG;
        const int k0 = c * 64;
        #pragma unroll
        for (int v = tid; v < TOTU; v += 256) {
            const __half* src; __half* d;
            int row = v >> 3, q = v & 7;
            if (row < 128) {
                src = A + (size_t)(m0 + row) * K + k0 + q * 8;
                d   = dst + row * LDSR + q * 8;
            } else {
                int r2 = row - 128;
                src = W + (size_t)(n0 + r2) * K + k0 + q * 8;
                d   = dst + ABUF + r2 * LDSR + q * 8;
            }
            CP_ASYNC16((uint32_t)__cvta_generic_to_shared(d), src);
        }
        CP_COMMIT();
    };

    load_chunk(0, 0);
    for (int c = 0; c < NC; c++) {
        const int p = c & 1;
        if (c + 1 < NC) { load_chunk(c + 1, p ^ 1); CP_WAIT1(); }
        else            { CP_WAIT0(); }
        __syncthreads();

        const uint32_t sA = sbase + (uint32_t)(p * STG) * 2;
        const uint32_t sB = sA + (uint32_t)ABUF * 2;
        #pragma unroll
        for (int kk = 0; kk < 64; kk += 16) {
            uint32_t a[4][4], b[NT][2];
            #pragma unroll
            for (int mi = 0; mi < 4; mi++) {
                const int r0 = wm * 64 + mi * 16;
                ldsm_x4(a[mi], sA + (uint32_t)((r0 + a_row) * LDSR + kk + a_k) * 2);
            }
            #pragma unroll
            for (int np = 0; np < NT / 2; np++) {
                const int c0 = wn * NT * 8 + np * 16;
                uint32_t bb4[4];
                ldsm_x4(bb4, sB + (uint32_t)((c0 + b_col) * LDSR + kk + b_k) * 2);
                b[2*np][0] = bb4[0]; b[2*np][1] = bb4[1];
                b[2*np+1][0] = bb4[2]; b[2*np+1][1] = bb4[3];
            }
            #pragma unroll
            for (int mi = 0; mi < 4; mi++)
                #pragma unroll
                for (int ni = 0; ni < NT; ni++)
                    mma_f16(acc[mi][ni], a[mi], b[ni]);
        }
        __syncthreads();
    }

    #pragma unroll
    for (int mi = 0; mi < 4; mi++) {
        const int row = m0 + wm * 64 + mi * 16 + g;
        #pragma unroll
        for (int ni = 0; ni < NT; ni++) {
            const int col = n0 + wn * NT * 8 + ni * 8 + 2 * t;
            float2 bv = *(const float2*)&bias[col];
            float o0 = acc[mi][ni][0] + bv.x;
            float o1 = acc[mi][ni][1] + bv.y;
            float o2 = acc[mi][ni][2] + bv.x;
            float o3 = acc[mi][ni][3] + bv.y;
            if (EPI == 1) {
                o0 = gelu_exact(o0); o1 = gelu_exact(o1);
                o2 = gelu_exact(o2); o3 = gelu_exact(o3);
            } else if (EPI == 2) {
                float2 r0 = *(const float2*)&R[(size_t)row * Nn + col];
                float2 r1 = *(const float2*)&R[(size_t)(row + 8) * Nn + col];
                o0 += r0.x; o1 += r0.y; o2 += r1.x; o3 += r1.y;
            }
            if (OUTH) {
                __half* C = (__half*)Cv;
                *(__half2*)&C[(size_t)row * Nn + col] = __floats2half2_rn(o0, o1);
                *(__half2*)&C[(size_t)(row + 8) * Nn + col] = __floats2half2_rn(o2, o3);
            } else {
                float* C = (float*)Cv;
                *(float2*)&C[(size_t)row * Nn + col] = make_float2(o0, o1);
                *(float2*)&C[(size_t)(row + 8) * Nn + col] = make_float2(o2, o3);
            }
        }
    }
}

// ================= scaled-fp16-split GEMM (fp32-grade) for f projection =================
__global__ void __launch_bounds__(256) fsplit16_gemm(
    const __half* __restrict__ Ah, const __half* __restrict__ Al,
    const __half* __restrict__ Wh, const __half* __restrict__ Wl,
    const float* __restrict__ bias, float* __restrict__ C, int M, int Nn, int K)
{
    extern __shared__ __half smh[];
    constexpr int BN = 64;
    constexpr int LDSR = 40;
    constexpr int ABUF = 128 * LDSR;
    constexpr int BBUF = BN * LDSR;
    constexpr int STG  = 2 * ABUF + 2 * BBUF;
    constexpr int NT   = BN / 32;
    constexpr int AU   = 128 * 4;
    constexpr int WU   = BN * 4;
    constexpr int TOTU = 2 * AU + 2 * WU;

    const int tid  = threadIdx.x;
    const int lane = tid & 31, warp = tid >> 5;
    const int wm = warp & 1, wn = warp >> 1;
    const int g = lane >> 2, t = lane & 3;
    const int m0 = blockIdx.y * 128;
    const int n0 = blockIdx.x * BN;
    const int NC = K / 32;

    float ach[4][NT][4], acl[4][NT][4];
    #pragma unroll
    for (int mi = 0; mi < 4; mi++)
        #pragma unroll
        for (int ni = 0; ni < NT; ni++)
            #pragma unroll
            for (int r = 0; r < 4; r++) { ach[mi][ni][r] = 0.f; acl[mi][ni][r] = 0.f; }

    auto load_chunk = [&](int c, int p) {
        __half* dst = smh + p * STG;
        const int k0 = c * 32;
        #pragma unroll
        for (int v = tid; v < TOTU; v += 256) {
            const __half* src; __half* d;
            if (v < AU) {
                int row = v >> 2, q = v & 3;
                src = Ah + (size_t)(m0 + row) * K + k0 + q * 8;
                d   = dst + row * LDSR + q * 8;
            } else if (v < 2 * AU) {
                int u = v - AU; int row = u >> 2, q = u & 3;
                src = Al + (size_t)(m0 + row) * K + k0 + q * 8;
                d   = dst + ABUF + row * LDSR + q * 8;
            } else if (v < 2 * AU + WU) {
                int u = v - 2 * AU; int row = u >> 2, q = u & 3;
                src = Wh + (size_t)(n0 + row) * K + k0 + q * 8;
                d   = dst + 2 * ABUF + row * LDSR + q * 8;
            } else {
                int u = v - 2 * AU - WU; int row = u >> 2, q = u & 3;
                src = Wl + (size_t)(n0 + row) * K + k0 + q * 8;
                d   = dst + 2 * ABUF + BBUF + row * LDSR + q * 8;
            }
            CP_ASYNC16((uint32_t)__cvta_generic_to_shared(d), src);
        }
        CP_COMMIT();
    };

    load_chunk(0, 0);
    for (int c = 0; c < NC; c++) {
        const int p = c & 1;
        if (c + 1 < NC) { load_chunk(c + 1, p ^ 1); CP_WAIT1(); }
        else            { CP_WAIT0(); }
        __syncthreads();

        const __half* Ash = smh + p * STG;
        const __half* Asl = Ash + ABUF;
        const __half* Wsh = Ash + 2 * ABUF;
        const __half* Wsl = Wsh + BBUF;
        #pragma unroll
        for (int kk = 0; kk < 32; kk += 16) {
            uint32_t ah[4][4], al[4][4], bh[NT][2], bl[NT][2];
            #pragma unroll
            for (int mi = 0; mi < 4; mi++) {
                const int r0 = wm * 64 + mi * 16 + g;
                ah[mi][0] = *(const uint32_t*)&Ash[r0 * LDSR + kk + 2 * t];
                ah[mi][1] = *(const uint32_t*)&Ash[(r0 + 8) * LDSR + kk + 2 * t];
                ah[mi][2] = *(const uint32_t*)&Ash[r0 * LDSR + kk + 8 + 2 * t];
                ah[mi][3] = *(const uint32_t*)&Ash[(r0 + 8) * LDSR + kk + 8 + 2 * t];
                al[mi][0] = *(const uint32_t*)&Asl[r0 * LDSR + kk + 2 * t];
                al[mi][1] = *(const uint32_t*)&Asl[(r0 + 8) * LDSR + kk + 2 * t];
                al[mi][2] = *(const uint32_t*)&Asl[r0 * LDSR + kk + 8 + 2 * t];
                al[mi][3] = *(const uint32_t*)&Asl[(r0 + 8) * LDSR + kk + 8 + 2 * t];
            }
            #pragma unroll
            for (int ni = 0; ni < NT; ni++) {
                const int c0 = wn * NT * 8 + ni * 8 + g;
                bh[ni][0] = *(const uint32_t*)&Wsh[c0 * LDSR + kk + 2 * t];
                bh[ni][1] = *(const uint32_t*)&Wsh[c0 * LDSR + kk + 8 + 2 * t];
                bl[ni][0] = *(const uint32_t*)&Wsl[c0 * LDSR + kk + 2 * t];
                bl[ni][1] = *(const uint32_t*)&Wsl[c0 * LDSR + kk + 8 + 2 * t];
            }
            #pragma unroll
            for (int mi = 0; mi < 4; mi++)
                #pragma unroll
                for (int ni = 0; ni < NT; ni++) {
                    mma_f16(ach[mi][ni], ah[mi], bh[ni]);
                    mma_f16(acl[mi][ni], ah[mi], bl[ni]);
                    mma_f16(acl[mi][ni], al[mi], bh[ni]);
                }
        }
        __syncthreads();
    }

    #pragma unroll
    for (int mi = 0; mi < 4; mi++) {
        const int row = m0 + wm * 64 + mi * 16 + g;
        #pragma unroll
        for (int ni = 0; ni < NT; ni++) {
            const int col = n0 + wn * NT * 8 + ni * 8 + 2 * t;
            float2 bv = *(const float2*)&bias[col];
            float o0 = fmaf(acl[mi][ni][0], SPLIT_ISCALE, ach[mi][ni][0]) + bv.x;
            float o1 = fmaf(acl[mi][ni][1], SPLIT_ISCALE, ach[mi][ni][1]) + bv.y;
            float o2 = fmaf(acl[mi][ni][2], SPLIT_ISCALE, ach[mi][ni][2]) + bv.x;
            float o3 = fmaf(acl[mi][ni][3], SPLIT_ISCALE, ach[mi][ni][3]) + bv.y;
            *(float2*)&C[(size_t)row * Nn + col] = make_float2(o0, o1);
            *(float2*)&C[(size_t)(row + 8) * Nn + col] = make_float2(o2, o3);
        }
    }
}

// ---------------- fused fp32 -> fp16 conversion for v/proj/fc1/fc2 weights ----------------
#define N4_VW   (INNER*DD/4)     // 36864
#define N4_PW   (DD*INNER/4)     // 36864
#define N4_F1W  (HID*DD/4)       // 589824
#define N4_F2W  (DD*HID/4)       // 589824
#define N4_ALL  (N4_VW + N4_PW + N4_F1W + N4_F2W)

__global__ void __launch_bounds__(256) cvt_all_kernel(
    const float* __restrict__ vw, const float* __restrict__ pw,
    const float* __restrict__ f1w, const float* __restrict__ f2w)
{
    int i = blockIdx.x * 256 + threadIdx.x;
    if (i >= N4_ALL) return;
    const float* src; __half* dst; int j = i;
    __half *p_vwh = g_vwh, *p_pwh = g_pwh, *p_f1 = g_f1wh, *p_f2 = g_f2wh;
    if (j < N4_VW) { src = vw; dst = p_vwh; }
    else if ((j -= N4_VW) < N4_PW) { src = pw; dst = p_pwh; }
    else if ((j -= N4_PW) < N4_F1W) { src = f1w; dst = p_f1; }
    else { j -= N4_F1W; src = f2w; dst = p_f2; }
    float4 v = *(const float4*)&src[(size_t)j * 4];
    __half2* d = (__half2*)&dst[(size_t)j * 4];
    d[0] = __floats2half2_rn(v.x, v.y);
    d[1] = __floats2half2_rn(v.z, v.w);
}

// ---------------- fp32 -> fp16 hi/lo split conversion (f weights) ----------------
__global__ void __launch_bounds__(256) cvt_split_kernel(const float* __restrict__ src,
    __half* __restrict__ dh, __half* __restrict__ dl, int n4)
{
    int i = blockIdx.x * 256 + threadIdx.x;
    if (i >= n4) return;
    float4 v = *(const float4*)&src[i * 4];
    __half h0 = __float2half_rn(v.x), h1 = __float2half_rn(v.y);
    __half h2 = __float2half_rn(v.z), h3 = __float2half_rn(v.w);
    __half2* ph = (__half2*)&dh[i * 4];
    ph[0] = __halves2half2(h0, h1);
    ph[1] = __halves2half2(h2, h3);
    __half2* pl = (__half2*)&dl[i * 4];
    pl[0] = __floats2half2_rn((v.x - __half2float(h0)) * SPLIT_SCALE,
                              (v.y - __half2float(h1)) * SPLIT_SCALE);
    pl[1] = __floats2half2_rn((v.z - __half2float(h2)) * SPLIT_SCALE,
                              (v.w - __half2float(h3)) * SPLIT_SCALE);
}

// ---------------- LayerNorm ----------------
__global__ void __launch_bounds__(256) ln_kernel(const float* __restrict__ x,
    const float* __restrict__ w, const float* __restrict__ b,
    __half* __restrict__ outh, __half* __restrict__ outl)
{
    int t = blockIdx.x;
    const float* xr = x + (size_t)t * DD;
    int tid = threadIdx.x;
    float v0 = xr[tid], v1 = xr[tid + 256], v2 = xr[tid + 512];
    float s  = v0 + v1 + v2;
    float ss = v0*v0 + v1*v1 + v2*v2;
    #pragma unroll
    for (int o = 16; o; o >>= 1) {
        s  += __shfl_xor_sync(0xffffffffu, s,  o);
        ss += __shfl_xor_sync(0xffffffffu, ss, o);
    }
    __shared__ float rs[8], rss[8];
    if ((tid & 31) == 0) { rs[tid >> 5] = s; rss[tid >> 5] = ss; }
    __syncthreads();
    float S = 0.f, SS = 0.f;
    #pragma unroll
    for (int i = 0; i < 8; i++) { S += rs[i]; SS += rss[i]; }
    float mean = S * (1.f / DD);
    float var  = SS * (1.f / DD) - mean * mean;
    float rstd = rsqrtf(var + 1e-5f);
    float o0 = (v0 - mean) * rstd * w[tid]       + b[tid];
    float o1 = (v1 - mean) * rstd * w[tid + 256] + b[tid + 256];
    float o2 = (v2 - mean) * rstd * w[tid + 512] + b[tid + 512];
    __half h0 = __float2half_rn(o0), h1 = __float2half_rn(o1), h2 = __float2half_rn(o2);
    __half* hrow = outh + (size_t)t * DD;
    hrow[tid] = h0; hrow[tid + 256] = h1; hrow[tid + 512] = h2;
    if (outl) {
        __half* lrow = outl + (size_t)t * DD;
        lrow[tid]       = __float2half_rn((o0 - __half2float(h0)) * SPLIT_SCALE);
        lrow[tid + 256] = __float2half_rn((o1 - __half2float(h1)) * SPLIT_SCALE);
        lrow[tid + 512] = __float2half_rn((o2 - __half2float(h2)) * SPLIT_SCALE);
    }
}

// ---------------- Pooling: one block per (center, be) ----------------
__global__ void __launch_bounds__(192) pool_kernel()
{
    int m  = blockIdx.x;     // 0..15
    int be = blockIdx.y;     // 0..127
    int bb = be >> 3, e = be & 7;
    int tid = threadIdx.x;   // 192 = 24 c x 8 token-groups
    int c = tid % HDIM, grp = tid / HDIM;
    int pw = m >> 2, ph = m & 3;
    float sf = 0.f, sv = 0.f;
    #pragma unroll
    for (int j = 0; j < 8; j++) {
        int tt = grp * 8 + j;          // 0..63
        int ws = tt >> 3, hs = tt & 7;
        int n = (pw * 8 + ws) * PS + ph * 8 + hs;
        size_t idx = (size_t)(bb * NTOK + n) * INNER + e * HDIM + c;
        sf += g_f[idx];
        sv += g_v[idx];
    }
    __shared__ float pf[8][HDIM], pv[8][HDIM], sfin[HDIM];
    pf[grp][c] = sf; pv[grp][c] = sv;
    __syncthreads();
    if (grp == 0) {
        float tf = 0.f, tv = 0.f;
        #pragma unroll
        for (int gg = 0; gg < 8; gg++) { tf += pf[gg][c]; tv += pv[gg][c]; }
        tf *= (1.f / 64.f); tv *= (1.f / 64.f);
        sfin[c] = tf;
        size_t oidx = ((size_t)be * MCEN + m) * HDIM + c;
        g_vcen[oidx] = tv;
    }
    __syncthreads();
    if (grp == 0) {
        float ssq = 0.f;
        #pragma unroll
        for (int cc = 0; cc < HDIM; cc++) { float q = sfin[cc]; ssq += q * q; }
        float denom = fmaxf(sqrtf(ssq), 1e-12f);
        size_t oidx = ((size_t)be * MCEN + m) * HDIM + c;
        g_cn[oidx] = sfin[c] / denom;
    }
}

// ---------------- Assignment ----------------
__global__ void __launch_bounds__(256) assign_kernel(const float* __restrict__ alpha_p,
                                                     const float* __restrict__ beta_p)
{
    int be = blockIdx.x;
    int bb = be >> 3, e = be & 7;
    int nbase = blockIdx.y * 256;
    __shared__ float cns[MCEN][HDIM];
    for (int t = threadIdx.x; t < MCEN * HDIM; t += blockDim.x)
        cns[t / HDIM][t % HDIM] = g_cn[(size_t)be * MCEN * HDIM + t];
    __syncthreads();
    float alpha = *alpha_p, beta = *beta_p;
    int n = nbase + threadIdx.x;
    {
        const float* xv = g_f + (size_t)(bb * NTOK + n) * INNER + e * HDIM;
        float x[HDIM]; float ss = 0.f;
        #pragma unroll
        for (int c = 0; c < HDIM; c++) { x[c] = xv[c]; ss += x[c] * x[c]; }
        float inv = 1.f / fmaxf(sqrtf(ss), 1e-12f);
        float best = -1e30f; int bm = 0;
        #pragma unroll
        for (int m = 0; m < MCEN; m++) {
            float d = 0.f;
            #pragma unroll
            for (int c = 0; c < HDIM; c++) d = fmaf(cns[m][c], x[c], d);
            d *= inv;
            float dist = sqrtf(fmaxf(2.f - 2.f * d, 1e-12f));
            float sp = beta + alpha * expf(-dist);
            float sim = sp > 0.f ? sp : 0.2f * sp;
            if (sim > best) { best = sim; bm = m; }
        }
        g_assign[(size_t)be * NTOK + n] = bm;
        g_simval[(size_t)be * NTOK + n] = best;
    }
}

// ---------------- Weighted reduce to centers ----------------
__global__ void __launch_bounds__(192) outc_kernel()
{
    int m  = blockIdx.x;
    int be = blockIdx.y;
    int bb = be >> 3, e = be & 7;
    int tid = threadIdx.x;
    int c = tid % HDIM, g = tid / HDIM;
    float acc = 0.f; int cnt = 0;
    for (int n = g * 128; n < g * 128 + 128; n++) {
        int a = g_assign[(size_t)be * NTOK + n];
        if (a == m) {
            float s = g_simval[(size_t)be * NTOK + n];
            acc = fmaf(s, g_v[(size_t)(bb * NTOK + n) * INNER + e * HDIM + c], acc);
            cnt++;
        }
    }
    __shared__ float pa[8][HDIM];
    __shared__ int   pc[8];
    pa[g][c] = acc;
    if (c == 0) pc[g] = cnt;
    __syncthreads();
    if (g == 0) {
        float tot = 0.f; int ct = 0;
        #pragma unroll
        for (int gg = 0; gg < 8; gg++) { tot += pa[gg][c]; ct += pc[gg]; }
        size_t oidx = ((size_t)be * MCEN + m) * HDIM + c;
        g_outc[oidx] = (tot + g_vcen[oidx]) / ((float)ct + 1.f);
    }
}

// ---------------- Scatter ----------------
__global__ void __launch_bounds__(256) oi_kernel()
{
    size_t idx = (size_t)blockIdx.x * blockDim.x + threadIdx.x;
    if (idx >= (size_t)T_TOT * INNER) return;
    int t = (int)(idx / INNER), i = (int)(idx % INNER);
    int bb = t >> 10, n = t & (NTOK - 1);
    int e = i / HDIM, c = i % HDIM;
    int be = bb * HEADS + e;
    int m = g_assign[(size_t)be * NTOK + n];
    float val = g_simval[(size_t)be * NTOK + n] * g_outc[((size_t)be * MCEN + m) * HDIM + c];
    g_oih[idx] = __float2half_rn(val);
}

// ---------------- Launch ----------------
extern "C" void kernel_launch(void* const* d_in, const int* in_sizes, int n_in,
                              void* d_out, int out_size)
{
    const float* x      = (const float*)d_in[0];
    const float* ln1_w  = (const float*)d_in[1];
    const float* ln1_b  = (const float*)d_in[2];
    const float* f_w    = (const float*)d_in[3];
    const float* f_b    = (const float*)d_in[4];
    const float* v_w    = (const float*)d_in[5];
    const float* v_b    = (const float*)d_in[6];
    const float* proj_w = (const float*)d_in[7];
    const float* proj_b = (const float*)d_in[8];
    const float* alpha  = (const float*)d_in[9];
    const float* beta   = (const float*)d_in[10];
    const float* ln2_w  = (const float*)d_in[11];
    const float* ln2_b  = (const float*)d_in[12];
    const float* fc1_w  = (const float*)d_in[13];
    const float* fc1_b  = (const float*)d_in[14];
    const float* fc2_w  = (const float*)d_in[15];
    const float* fc2_b  = (const float*)d_in[16];
    float* out = (float*)d_out;

    float *p_f, *p_v, *p_h;
    __half *p_x1h, *p_x1l, *p_oih, *p_y1h, *p_acth;
    __half *p_fwh, *p_fwl, *p_vwh, *p_pwh, *p_f1wh, *p_f2wh;
    cudaGetSymbolAddress((void**)&p_x1h,  g_x1h);
    cudaGetSymbolAddress((void**)&p_x1l,  g_x1l);
    cudaGetSymbolAddress((void**)&p_f,    g_f);
    cudaGetSymbolAddress((void**)&p_v,    g_v);
    cudaGetSymbolAddress((void**)&p_oih,  g_oih);
    cudaGetSymbolAddress((void**)&p_h,    g_h);
    cudaGetSymbolAddress((void**)&p_y1h,  g_y1h);
    cudaGetSymbolAddress((void**)&p_acth, g_acth);
    cudaGetSymbolAddress((void**)&p_fwh,  g_fwh);
    cudaGetSymbolAddress((void**)&p_fwl,  g_fwl);
    cudaGetSymbolAddress((void**)&p_vwh,  g_vwh);
    cudaGetSymbolAddress((void**)&p_pwh,  g_pwh);
    cudaGetSymbolAddress((void**)&p_f1wh, g_f1wh);
    cudaGetSymbolAddress((void**)&p_f2wh, g_f2wh);

    const int SM_H128 = 2 * (128 + 128) * 72 * 2;        // 73728
    const int SM_H64  = 2 * (128 +  64) * 72 * 2;        // 55296
    const int SM_FS   = 2 * (2 * 128 * 40 + 2 * 64 * 40) * 2;  // 61440
    cudaFuncSetAttribute(fsplit16_gemm, cudaFuncAttributeMaxDynamicSharedMemorySize, SM_FS);
    cudaFuncSetAttribute(hgemm<64, 0, false>,  cudaFuncAttributeMaxDynamicSharedMemorySize, SM_H64);
    cudaFuncSetAttribute(hgemm<128, 1, true >, cudaFuncAttributeMaxDynamicSharedMemorySize, SM_H128);
    cudaFuncSetAttribute(hgemm<128, 2, false>, cudaFuncAttributeMaxDynamicSharedMemorySize, SM_H128);

    // 0) weight conversions
    cvt_split_kernel<<<(INNER * DD / 4 + 255) / 256, 256>>>(f_w, p_fwh, p_fwl, INNER * DD / 4);
    cvt_all_kernel<<<(N4_ALL + 255) / 256, 256>>>(v_w, proj_w, fc1_w, fc2_w);

    // 1) LN1 -> fp16 hi + scaled lo
    ln_kernel<<<T_TOT, 256>>>(x, ln1_w, ln1_b, p_x1h, p_x1l);

    // 2) f projection (scaled-fp16 split, fp32-grade)
    fsplit16_gemm<<<dim3(INNER / 64, T_TOT / 128), 256, SM_FS>>>(
        p_x1h, p_x1l, p_fwh, p_fwl, f_b, p_f, T_TOT, INNER, DD);
    // 3) v projection
    hgemm<64, 0, false><<<dim3(INNER / 64, T_TOT / 128), 256, SM_H64>>>(
        p_x1h, p_vwh, v_b, nullptr, p_v, T_TOT, INNER, DD);

    // 4-7) cluster path
    pool_kernel<<<dim3(MCEN, BE), 192>>>();
    assign_kernel<<<dim3(BE, NTOK / 256), 256>>>(alpha, beta);
    outc_kernel<<<dim3(MCEN, BE), 192>>>();
    oi_kernel<<<(T_TOT * INNER + 255) / 256, 256>>>();

    // 8) proj + residual x -> h
    hgemm<128, 2, false><<<dim3(DD / 128, T_TOT / 128), 256, SM_H128>>>(
        p_oih, p_pwh, proj_b, x, p_h, T_TOT, DD, INNER);

    // 9) LN2 -> fp16
    ln_kernel<<<T_TOT, 256>>>(p_h, ln2_w, ln2_b, p_y1h, nullptr);

    // 10) fc1 + GELU -> fp16 activations
    hgemm<128, 1, true><<<dim3(HID / 128, T_TOT / 128), 256, SM_H128>>>(
        p_y1h, p_f1wh, fc1_b, nullptr, p_acth, T_TOT, HID, DD);

    // 11) fc2 + residual h -> out
    hgemm<128, 2, false><<<dim3(DD / 128, T_TOT / 128), 256, SM_H128>>>(
        p_acth, p_f2wh, fc2_b, p_h, out, T_TOT, DD, HID);
}